// round 8
// baseline (speedup 1.0000x reference)
#include <cuda_runtime.h>
#include <cuda_bf16.h>
#include <cstdint>

#define T_LEN 2048
#define D_MODEL 1024
#define H_NUM 16
#define HS 64
#define CHUNK 128
#define NC 16
#define EPSF 1e-6f
#define SCP 80

// ---------------- scratch ----------------
__device__ float g_Sc [H_NUM * NC * HS * SCP];
__device__ __align__(16) __nv_bfloat16 g_sph[H_NUM * NC * HS * SCP];
__device__ __align__(16) __nv_bfloat16 g_spl[H_NUM * NC * HS * SCP];

__device__ __align__(16) __nv_bfloat16 g_qkvh[3][H_NUM][T_LEN][HS];
__device__ __align__(16) __nv_bfloat16 g_qkvl[3][H_NUM][T_LEN][HS];

__device__ __align__(16) __nv_bfloat16 g_ah [T_LEN * D_MODEL];
__device__ __align__(16) __nv_bfloat16 g_al [T_LEN * D_MODEL];
__device__ __align__(16) __nv_bfloat16 g_b2h[D_MODEL * D_MODEL];
__device__ __align__(16) __nv_bfloat16 g_b2l[D_MODEL * D_MODEL];

// int8 limbs + per-row scales (GEMM1)
__device__ __align__(16) int8_t g_xa0[T_LEN * D_MODEL];
__device__ __align__(16) int8_t g_xa1[T_LEN * D_MODEL];
__device__ float g_sa[T_LEN];
__device__ __align__(16) int8_t g_wb0[3 * D_MODEL * D_MODEL];
__device__ __align__(16) int8_t g_wb1[3 * D_MODEL * D_MODEL];
__device__ float g_sb[3 * D_MODEL];

__device__ __forceinline__ float phi(float x) {
    return x > 0.f ? x + 1.f : expf(x);
}
__device__ __forceinline__ void split1(float x, __nv_bfloat16& h, __nv_bfloat16& l) {
    h = __float2bfloat16_rn(x);
    l = __float2bfloat16_rn(x - __bfloat162float(h));
}
__device__ __forceinline__ void split2(float a, float b, uint32_t& hi, uint32_t& lo) {
    __nv_bfloat16 ha, la, hb, lb;
    split1(a, ha, la);
    split1(b, hb, lb);
    hi = (uint32_t)__bfloat16_as_ushort(ha) | ((uint32_t)__bfloat16_as_ushort(hb) << 16);
    lo = (uint32_t)__bfloat16_as_ushort(la) | ((uint32_t)__bfloat16_as_ushort(lb) << 16);
}

__global__ __launch_bounds__(256) void splitk(const float* __restrict__ s,
                                              __nv_bfloat16* __restrict__ h,
                                              __nv_bfloat16* __restrict__ l,
                                              int n4) {
    int i = blockIdx.x * 256 + threadIdx.x;
    if (i >= n4) return;
    float4 v = ((const float4*)s)[i];
    uint32_t h01, l01, h23, l23;
    split2(v.x, v.y, h01, l01);
    split2(v.z, v.w, h23, l23);
    ((uint2*)h)[i] = make_uint2(h01, h23);
    ((uint2*)l)[i] = make_uint2(l01, l23);
}

// ---- fp32 row(1024) -> 2x int8 limbs + scale ----
__global__ __launch_bounds__(256) void quant_rows(const float* __restrict__ src,
                                                  int8_t* __restrict__ L0,
                                                  int8_t* __restrict__ L1,
                                                  float* __restrict__ scale) {
    __shared__ float red[8];
    const int row = blockIdx.x, tid = threadIdx.x;
    float4 v = ((const float4*)(src + (size_t)row * 1024))[tid];
    float m = fmaxf(fmaxf(fabsf(v.x), fabsf(v.y)), fmaxf(fabsf(v.z), fabsf(v.w)));
#pragma unroll
    for (int o = 16; o > 0; o >>= 1)
        m = fmaxf(m, __shfl_xor_sync(0xffffffffu, m, o));
    if ((tid & 31) == 0) red[tid >> 5] = m;
    __syncthreads();
    if (tid < 8) {
        float t = red[tid];
#pragma unroll
        for (int o = 4; o > 0; o >>= 1)
            t = fmaxf(t, __shfl_xor_sync(0xffu, t, o));
        if (tid == 0) red[0] = fmaxf(t, 1e-20f);
    }
    __syncthreads();
    float inv = 126.f / red[0];
    float f[4] = {v.x, v.y, v.z, v.w};
    char c0[4], c1[4];
#pragma unroll
    for (int j = 0; j < 4; j++) {
        float t = f[j] * inv;
        int l0 = __float2int_rn(t);
        int l1 = __float2int_rn((t - (float)l0) * 128.f);
        c0[j] = (char)l0;
        c1[j] = (char)l1;
    }
    ((char4*)(L0 + (size_t)row * 1024))[tid] = make_char4(c0[0], c0[1], c0[2], c0[3]);
    ((char4*)(L1 + (size_t)row * 1024))[tid] = make_char4(c1[0], c1[1], c1[2], c1[3]);
    if (tid == 0) scale[row] = red[0] / 126.f;
}

// ---------------- mma helpers ----------------
__device__ __forceinline__ uint32_t smem_u32(const void* p) {
    uint32_t a;
    asm("{ .reg .u64 t; cvta.to.shared.u64 t, %1; cvt.u32.u64 %0, t; }" : "=r"(a) : "l"(p));
    return a;
}
__device__ __forceinline__ void ldsm4(uint32_t* r, uint32_t addr) {
    asm volatile("ldmatrix.sync.aligned.m8n8.x4.shared.b16 {%0,%1,%2,%3}, [%4];"
                 : "=r"(r[0]), "=r"(r[1]), "=r"(r[2]), "=r"(r[3]) : "r"(addr));
}
__device__ __forceinline__ void ldsm4t(uint32_t* r, uint32_t addr) {
    asm volatile("ldmatrix.sync.aligned.m8n8.x4.trans.shared.b16 {%0,%1,%2,%3}, [%4];"
                 : "=r"(r[0]), "=r"(r[1]), "=r"(r[2]), "=r"(r[3]) : "r"(addr));
}
__device__ __forceinline__ void mma16816(float* d, const uint32_t* a, const uint32_t* b) {
    asm volatile("mma.sync.aligned.m16n8k16.row.col.f32.bf16.bf16.f32 "
                 "{%0,%1,%2,%3},{%4,%5,%6,%7},{%8,%9},{%0,%1,%2,%3};"
                 : "+f"(d[0]), "+f"(d[1]), "+f"(d[2]), "+f"(d[3])
                 : "r"(a[0]), "r"(a[1]), "r"(a[2]), "r"(a[3]), "r"(b[0]), "r"(b[1]));
}
__device__ __forceinline__ void mma_i8(int* d, const uint32_t* a, const uint32_t* b) {
    asm volatile("mma.sync.aligned.m16n8k32.row.col.s32.s8.s8.s32 "
                 "{%0,%1,%2,%3},{%4,%5,%6,%7},{%8,%9},{%0,%1,%2,%3};"
                 : "+r"(d[0]), "+r"(d[1]), "+r"(d[2]), "+r"(d[3])
                 : "r"(a[0]), "r"(a[1]), "r"(a[2]), "r"(a[3]), "r"(b[0]), "r"(b[1]));
}
#define CP16(dst, src) \
    asm volatile("cp.async.cg.shared.global [%0], [%1], 16;" :: "r"(dst), "l"(src) : "memory")
#define CP_COMMIT() asm volatile("cp.async.commit_group;" ::: "memory")
#define CP_WAIT0()  asm volatile("cp.async.wait_group 0;" ::: "memory")

// ============================================================================
// GEMM1 int8 2-limb: qkv = x @ w_qkv^T, fused dequant+phi+split epilogue.
// CTA 64x64, 8 warps of 16x32, BK=64, double buffer, 2 CTA/SM.
// smem tile rows: 64 bytes data + 16 pad = 80B pitch.
// ============================================================================
#define I8P 80
#define I8T (64 * I8P)                   /* 5120 */
#define STAGE8 (4 * I8T)                 /* 20480: A0,A1,B0,B1 */
#define GSM8 (2 * STAGE8)                /* 40960 */

__global__ __launch_bounds__(256, 2) void gemm_i8() {
    extern __shared__ char smem[];
    const uint32_t sb = smem_u32(smem);

    const int tid = threadIdx.x;
    const int wid = tid >> 5, lid = tid & 31;
    const int warp_m = wid & 3, warp_n = wid >> 2;
    const int m0 = blockIdx.y * 64, n0 = blockIdx.x * 64;

    const int a_row = lid & 15;
    const int a_ko  = (lid >> 4) * 16;           // bytes
    const int b_n   = (lid & 7) + ((lid >> 4) << 3);
    const int b_ko  = ((lid >> 3) & 1) * 16;     // bytes
    const int g = lid >> 2, tq = lid & 3;

    int P[3][4][4];
#pragma unroll
    for (int s = 0; s < 3; s++)
#pragma unroll
        for (int nb = 0; nb < 4; nb++)
#pragma unroll
            for (int e = 0; e < 4; e++) P[s][nb][e] = 0;

    auto load_stage = [&](uint32_t stg, int kb) {
#pragma unroll
        for (int j = 0; j < 4; j++) {
            int chunkid = tid + j * 256;          // 0..1023
            int tile = chunkid >> 8;              // A0,A1,B0,B1
            int within = chunkid & 255;
            int row = within >> 2, c = within & 3;
            const int8_t* base;
            if (tile == 0)      base = g_xa0 + (size_t)(m0 + row) * 1024;
            else if (tile == 1) base = g_xa1 + (size_t)(m0 + row) * 1024;
            else if (tile == 2) base = g_wb0 + (size_t)(n0 + row) * 1024;
            else                base = g_wb1 + (size_t)(n0 + row) * 1024;
            CP16(stg + tile * I8T + row * I8P + c * 16, base + kb * 64 + c * 16);
        }
        CP_COMMIT();
    };

    load_stage(sb, 0);
    CP_WAIT0();
    __syncthreads();

#pragma unroll 1
    for (int kb = 0; kb < 16; kb++) {
        const uint32_t stage = sb + (kb & 1) * STAGE8;
        if (kb + 1 < 16) load_stage(sb + ((kb + 1) & 1) * STAGE8, kb + 1);

#pragma unroll
        for (int ks = 0; ks < 2; ks++) {
            uint32_t aa[2][4];
            ldsm4(aa[0], stage + 0 * I8T + (warp_m * 16 + a_row) * I8P + ks * 32 + a_ko);
            ldsm4(aa[1], stage + 1 * I8T + (warp_m * 16 + a_row) * I8P + ks * 32 + a_ko);
#pragma unroll
            for (int limB = 0; limB < 2; limB++) {
#pragma unroll
                for (int nh = 0; nh < 2; nh++) {
                    uint32_t bb[4];
                    ldsm4(bb, stage + (2 + limB) * I8T +
                              (warp_n * 32 + nh * 16 + b_n) * I8P + ks * 32 + b_ko);
#pragma unroll
                    for (int limA = 0; limA < 2; limA++) {
                        int s = limA + limB;
                        mma_i8(P[s][nh * 2 + 0], aa[limA], &bb[0]);
                        mma_i8(P[s][nh * 2 + 1], aa[limA], &bb[2]);
                    }
                }
            }
        }

        if (kb + 1 < 16) CP_WAIT0();
        __syncthreads();
    }

    // epilogue: dequant + phi + bf16 split -> g_qkv{h,l}
    const int sq  = n0 >> 10;
    const int hh2 = (n0 >> 6) & 15;
    const int r_lo = m0 + warp_m * 16 + g, r_hi = r_lo + 8;
    const float sa_lo = g_sa[r_lo], sa_hi = g_sa[r_hi];
#pragma unroll
    for (int nb = 0; nb < 4; nb++) {
        int c0 = n0 + warp_n * 32 + nb * 8 + tq * 2;
        float sb0 = g_sb[c0], sb1 = g_sb[c0 + 1];
        const int* p0 = P[0][nb];
        const int* p1 = P[1][nb];
        const int* p2 = P[2][nb];
        float d0 = (float)p0[0] + (float)p1[0] * 0.0078125f + (float)p2[0] * 6.103515625e-5f;
        float d1 = (float)p0[1] + (float)p1[1] * 0.0078125f + (float)p2[1] * 6.103515625e-5f;
        float d2 = (float)p0[2] + (float)p1[2] * 0.0078125f + (float)p2[2] * 6.103515625e-5f;
        float d3 = (float)p0[3] + (float)p1[3] * 0.0078125f + (float)p2[3] * 6.103515625e-5f;
        float v00 = sa_lo * sb0 * d0, v01 = sa_lo * sb1 * d1;
        float v10 = sa_hi * sb0 * d2, v11 = sa_hi * sb1 * d3;
        if (sq < 2) { v00 = phi(v00); v01 = phi(v01); v10 = phi(v10); v11 = phi(v11); }
        int dd = c0 & 63;
        uint32_t hw, lw;
        split2(v00, v01, hw, lw);
        *(uint32_t*)&g_qkvh[sq][hh2][r_lo][dd] = hw;
        *(uint32_t*)&g_qkvl[sq][hh2][r_lo][dd] = lw;
        split2(v10, v11, hw, lw);
        *(uint32_t*)&g_qkvh[sq][hh2][r_hi][dd] = hw;
        *(uint32_t*)&g_qkvl[sq][hh2][r_hi][dd] = lw;
    }
}

// ============================================================================
// GEMM2 split-bf16 (R6 core): out = xo @ w_out^T
// ============================================================================
#define TPITCH 80
#define TILE_B (128 * TPITCH)
#define STAGE_B (4 * TILE_B)
#define GSM_TOTAL (2 * STAGE_B)

__global__ __launch_bounds__(256, 2) void gemm_bf16s(
        const __nv_bfloat16* __restrict__ Ah, const __nv_bfloat16* __restrict__ Al,
        const __nv_bfloat16* __restrict__ Bh, const __nv_bfloat16* __restrict__ Bl,
        float* __restrict__ C, int M, int N, int K) {
    extern __shared__ char smem[];
    const uint32_t sb = smem_u32(smem);

    const int tid = threadIdx.x;
    const int wid = tid >> 5, lid = tid & 31;
    const int warp_m = wid & 3, warp_n = wid >> 2;
    const int m0 = blockIdx.y * 128, n0 = blockIdx.x * 128;
    const int NKB = K >> 5;

    const __nv_bfloat16* srcs[4] = {Ah, Al, Bh, Bl};

    const int a_row  = lid & 15;
    const int a_koff = (lid >> 4) * 8;
    const int b_n    = (lid & 7) + ((lid >> 4) << 3);
    const int b_ko   = ((lid >> 3) & 1) * 8;
    const int g = lid >> 2, tg = lid & 3;

    float acc[2][8][4];
#pragma unroll
    for (int i = 0; i < 2; i++)
#pragma unroll
        for (int j = 0; j < 8; j++)
#pragma unroll
            for (int k = 0; k < 4; k++) acc[i][j][k] = 0.f;

#pragma unroll
    for (int j = 0; j < 8; j++) {
        int chunkid = tid + j * 256;
        int tile = chunkid >> 9;
        int within = chunkid & 511;
        int row = within >> 2, c = within & 3;
        int grow = (tile < 2 ? m0 : n0) + row;
        CP16(sb + tile * TILE_B + row * TPITCH + c * 16,
             srcs[tile] + (size_t)grow * K + c * 8);
    }
    CP_COMMIT();
    CP_WAIT0();
    __syncthreads();

#pragma unroll 1
    for (int kb = 0; kb < NKB; kb++) {
        const int s = kb & 1;
        const uint32_t stage = sb + s * STAGE_B;

        if (kb + 1 < NKB) {
            const uint32_t nstage = sb + (1 - s) * STAGE_B;
#pragma unroll
            for (int j = 0; j < 8; j++) {
                int chunkid = tid + j * 256;
                int tile = chunkid >> 9;
                int within = chunkid & 511;
                int row = within >> 2, c = within & 3;
                int grow = (tile < 2 ? m0 : n0) + row;
                CP16(nstage + tile * TILE_B + row * TPITCH + c * 16,
                     srcs[tile] + (size_t)grow * K + (kb + 1) * 32 + c * 8);
            }
            CP_COMMIT();
        }

        const uint32_t tAh = stage;
        const uint32_t tAl = stage + TILE_B;
        const uint32_t tBh = stage + 2 * TILE_B;
        const uint32_t tBl = stage + 3 * TILE_B;

#pragma unroll
        for (int ks = 0; ks < 2; ks++) {
            uint32_t a_h[2][4], a_l[2][4];
#pragma unroll
            for (int mt = 0; mt < 2; mt++) {
                uint32_t ao = (uint32_t)((warp_m * 32 + mt * 16 + a_row) * TPITCH +
                                         (ks * 16 + a_koff) * 2);
                ldsm4(a_h[mt], tAh + ao);
                ldsm4(a_l[mt], tAl + ao);
            }
            uint32_t bf[4][4];
#pragma unroll
            for (int ng = 0; ng < 4; ng++) {
                uint32_t bo = (uint32_t)((warp_n * 64 + ng * 16 + b_n) * TPITCH +
                                         (ks * 16 + b_ko) * 2);
                ldsm4(bf[ng], tBh + bo);
            }
#pragma unroll
            for (int ng = 0; ng < 4; ng++)
#pragma unroll
                for (int mt = 0; mt < 2; mt++) {
                    mma16816(acc[mt][ng * 2 + 0], a_h[mt], &bf[ng][0]);
                    mma16816(acc[mt][ng * 2 + 1], a_h[mt], &bf[ng][2]);
                }
#pragma unroll
            for (int ng = 0; ng < 4; ng++)
#pragma unroll
                for (int mt = 0; mt < 2; mt++) {
                    mma16816(acc[mt][ng * 2 + 0], a_l[mt], &bf[ng][0]);
                    mma16816(acc[mt][ng * 2 + 1], a_l[mt], &bf[ng][2]);
                }
#pragma unroll
            for (int ng = 0; ng < 4; ng++) {
                uint32_t bo = (uint32_t)((warp_n * 64 + ng * 16 + b_n) * TPITCH +
                                         (ks * 16 + b_ko) * 2);
                ldsm4(bf[ng], tBl + bo);
            }
#pragma unroll
            for (int ng = 0; ng < 4; ng++)
#pragma unroll
                for (int mt = 0; mt < 2; mt++) {
                    mma16816(acc[mt][ng * 2 + 0], a_h[mt], &bf[ng][0]);
                    mma16816(acc[mt][ng * 2 + 1], a_h[mt], &bf[ng][2]);
                }
        }

        if (kb + 1 < NKB) CP_WAIT0();
        __syncthreads();
    }

#pragma unroll
    for (int mt = 0; mt < 2; mt++) {
#pragma unroll
        for (int j = 0; j < 8; j++) {
            float* d = acc[mt][j];
            int r0 = m0 + warp_m * 32 + mt * 16 + g;
            int col = n0 + warp_n * 64 + j * 8 + tg * 2;
            *(float2*)(C + (size_t)r0 * N + col)       = make_float2(d[0], d[1]);
            *(float2*)(C + (size_t)(r0 + 8) * N + col) = make_float2(d[2], d[3]);
        }
    }
}

// ---------------- per-chunk KV sums ----------------
__global__ __launch_bounds__(256) void chunk_sums() {
    extern __shared__ float sm[];
    float* Ks = sm;
    float* Vs = sm + CHUNK * HS;
    int blk = blockIdx.x;
    int h = blk >> 4, cc = blk & 15;
    int t0 = cc * CHUNK;
    int tid = threadIdx.x;

    for (int i = tid; i < CHUNK * HS; i += 256) {
        int t = i >> 6, d = i & 63;
        Ks[i] = __bfloat162float(g_qkvh[1][h][t0 + t][d]) +
                __bfloat162float(g_qkvl[1][h][t0 + t][d]);
        Vs[i] = __bfloat162float(g_qkvh[2][h][t0 + t][d]) +
                __bfloat162float(g_qkvl[2][h][t0 + t][d]);
    }
    __syncthreads();

    int d0 = (tid >> 4) * 4, f0 = (tid & 15) * 4;
    float acc[4][4];
#pragma unroll
    for (int i = 0; i < 4; i++)
#pragma unroll
        for (int j = 0; j < 4; j++) acc[i][j] = 0.f;

    for (int t = 0; t < CHUNK; t++) {
        float4 k4 = *(const float4*)&Ks[t * HS + d0];
        float4 v4 = *(const float4*)&Vs[t * HS + f0];
        float kf[4] = {k4.x, k4.y, k4.z, k4.w};
        float vf[4] = {v4.x, v4.y, v4.z, v4.w};
#pragma unroll
        for (int i = 0; i < 4; i++)
#pragma unroll
            for (int j = 0; j < 4; j++)
                acc[i][j] = fmaf(kf[i], vf[j], acc[i][j]);
    }
    float* Sout = g_Sc + (size_t)blk * HS * SCP;
#pragma unroll
    for (int i = 0; i < 4; i++)
#pragma unroll
        for (int j = 0; j < 4; j++)
            Sout[(d0 + i) * SCP + f0 + j] = acc[i][j];

    if (tid < HS) {
        float z = 0.f;
        for (int t = 0; t < CHUNK; t++) z += Ks[t * HS + tid];
        Sout[tid * SCP + 64] = z;
    }
    for (int i = tid; i < HS * 15; i += 256) {
        int r = i / 15, c2 = 65 + i % 15;
        Sout[r * SCP + c2] = 0.f;
    }
}

// ---------------- exclusive prefix -> split bf16 Sp ----------------
__global__ __launch_bounds__(256) void chunk_prefix() {
    int h = blockIdx.x / 20;
    int e = (blockIdx.x % 20) * 256 + threadIdx.x;
    float run = 0.f;
#pragma unroll
    for (int c = 0; c < NC; c++) {
        size_t idx = (size_t)(h * NC + c) * (HS * SCP) + e;
        __nv_bfloat16 hh, ll;
        split1(run, hh, ll);
        g_sph[idx] = hh;
        g_spl[idx] = ll;
        run += g_Sc[idx];
    }
}

// ============================================================================
// attention per chunk (R6, unchanged)
// ============================================================================
#define QVP 144
#define SPB 176
#define OFF_QH 0
#define OFF_QL (1 * 128 * QVP)
#define OFF_KH (2 * 128 * QVP)
#define OFF_KL (3 * 128 * QVP)
#define OFF_VH (4 * 128 * QVP)
#define OFF_VL (5 * 128 * QVP)
#define OFF_SPH (6 * 128 * QVP)
#define OFF_SPL (OFF_SPH + 64 * SPB)
#define ATTN_SMEM_B (OFF_SPL + 64 * SPB)

__global__ __launch_bounds__(256) void attn_mma() {
    extern __shared__ char smc[];
    const uint32_t sb = smem_u32(smc);

    const int blk = blockIdx.x;
    const int h = blk >> 4, cc = blk & 15;
    const int t0g = cc * CHUNK;
    const int tid = threadIdx.x;
    const int w = tid >> 5, lid = tid & 31;

#pragma unroll
    for (int j = 0; j < 24; j++) {
        int chunkid = tid + j * 256;
        int buf = chunkid >> 10;
        int within = chunkid & 1023;
        int row = within >> 3, c = within & 7;
        int sidx = buf >> 1;
        const __nv_bfloat16* srcp = (buf & 1) ? &g_qkvl[sidx][h][t0g + row][0]
                                              : &g_qkvh[sidx][h][t0g + row][0];
        CP16(sb + buf * (128 * QVP) + row * QVP + c * 16, srcp + c * 8);
    }
#pragma unroll
    for (int j = 0; j < 5; j++) {
        int chunkid = tid + j * 256;
        int buf = chunkid / 640;
        int within = chunkid % 640;
        int row = within / 10, c = within % 10;
        const __nv_bfloat16* srcp = (buf ? g_spl : g_sph) + (size_t)blk * (HS * SCP) + row * SCP + c * 8;
        CP16(sb + OFF_SPH + buf * (64 * SPB) + row * SPB + c * 16, srcp);
    }
    CP_COMMIT();
    CP_WAIT0();
    __syncthreads();

    const int a_row  = lid & 15;
    const int a_koff = (lid >> 4) * 8;
    const int b_n    = (lid & 7) + ((lid >> 4) << 3);
    const int b_ko   = ((lid >> 3) & 1) * 8;
    const int t_row  = lid & 15;
    const int t_col  = ((lid >> 4) << 3);
    const int g = lid >> 2, tq = lid & 3;

    float ca[16][4];
#pragma unroll
    for (int j = 0; j < 16; j++)
#pragma unroll
        for (int e = 0; e < 4; e++) ca[j][e] = 0.f;

#pragma unroll
    for (int ks = 0; ks < 4; ks++) {
        uint32_t aqh[4], aql[4];
        uint32_t ao = (uint32_t)((w * 16 + a_row) * QVP + (ks * 16 + a_koff) * 2);
        ldsm4(aqh, sb + OFF_QH + ao);
        ldsm4(aql, sb + OFF_QL + ao);
#pragma unroll
        for (int sg = 0; sg < 8; sg++) {
            uint32_t bo = (uint32_t)((sg * 16 + b_n) * QVP + (ks * 16 + b_ko) * 2);
            uint32_t bkh[4], bkl[4];
            ldsm4(bkh, sb + OFF_KH + bo);
            ldsm4(bkl, sb + OFF_KL + bo);
            mma16816(ca[sg * 2 + 0], aqh, &bkh[0]);
            mma16816(ca[sg * 2 + 1], aqh, &bkh[2]);
            mma16816(ca[sg * 2 + 0], aqh, &bkl[0]);
            mma16816(ca[sg * 2 + 1], aqh, &bkl[2]);
            mma16816(ca[sg * 2 + 0], aql, &bkh[0]);
            mma16816(ca[sg * 2 + 1], aql, &bkh[2]);
        }
    }

    const int row_lo = w * 16 + g, row_hi = row_lo + 8;
    float s_lo = 0.f, s_hi = 0.f;
#pragma unroll
    for (int j = 0; j < 16; j++) {
        int c0 = j * 8 + tq * 2;
        if (c0     > row_lo) ca[j][0] = 0.f;
        if (c0 + 1 > row_lo) ca[j][1] = 0.f;
        if (c0     > row_hi) ca[j][2] = 0.f;
        if (c0 + 1 > row_hi) ca[j][3] = 0.f;
        s_lo += ca[j][0] + ca[j][1];
        s_hi += ca[j][2] + ca[j][3];
    }
    s_lo += __shfl_xor_sync(0xffffffffu, s_lo, 1);
    s_lo += __shfl_xor_sync(0xffffffffu, s_lo, 2);
    s_hi += __shfl_xor_sync(0xffffffffu, s_hi, 1);
    s_hi += __shfl_xor_sync(0xffffffffu, s_hi, 2);

    float co[10][4];
#pragma unroll
    for (int j = 0; j < 10; j++)
#pragma unroll
        for (int e = 0; e < 4; e++) co[j][e] = 0.f;

#pragma unroll
    for (int ks2 = 0; ks2 < 8; ks2++) {
        uint32_t ahf[4], alf[4];
        split2(ca[ks2 * 2 + 0][0], ca[ks2 * 2 + 0][1], ahf[0], alf[0]);
        split2(ca[ks2 * 2 + 0][2], ca[ks2 * 2 + 0][3], ahf[1], alf[1]);
        split2(ca[ks2 * 2 + 1][0], ca[ks2 * 2 + 1][1], ahf[2], alf[2]);
        split2(ca[ks2 * 2 + 1][2], ca[ks2 * 2 + 1][3], ahf[3], alf[3]);
#pragma unroll
        for (int fg = 0; fg < 4; fg++) {
            uint32_t bo = (uint32_t)((ks2 * 16 + t_row) * QVP + (fg * 16 + t_col) * 2);
            uint32_t bvh[4], bvl[4];
            ldsm4t(bvh, sb + OFF_VH + bo);
            ldsm4t(bvl, sb + OFF_VL + bo);
            mma16816(co[fg * 2 + 0], ahf, &bvh[0]);
            mma16816(co[fg * 2 + 1], ahf, &bvh[2]);
            mma16816(co[fg * 2 + 0], ahf, &bvl[0]);
            mma16816(co[fg * 2 + 1], ahf, &bvl[2]);
            mma16816(co[fg * 2 + 0], alf, &bvh[0]);
            mma16816(co[fg * 2 + 1], alf, &bvh[2]);
        }
    }

#pragma unroll
    for (int ks = 0; ks < 4; ks++) {
        uint32_t aqh[4], aql[4];
        uint32_t ao = (uint32_t)((w * 16 + a_row) * QVP + (ks * 16 + a_koff) * 2);
        ldsm4(aqh, sb + OFF_QH + ao);
        ldsm4(aql, sb + OFF_QL + ao);
#pragma unroll
        for (int fg = 0; fg < 5; fg++) {
            uint32_t bo = (uint32_t)((ks * 16 + t_row) * SPB + (fg * 16 + t_col) * 2);
            uint32_t bsh[4], bsl[4];
            ldsm4t(bsh, sb + OFF_SPH + bo);
            ldsm4t(bsl, sb + OFF_SPL + bo);
            mma16816(co[fg * 2 + 0], aqh, &bsh[0]);
            mma16816(co[fg * 2 + 1], aqh, &bsh[2]);
            mma16816(co[fg * 2 + 0], aqh, &bsl[0]);
            mma16816(co[fg * 2 + 1], aqh, &bsl[2]);
            mma16816(co[fg * 2 + 0], aql, &bsh[0]);
            mma16816(co[fg * 2 + 1], aql, &bsh[2]);
        }
    }

    float qz_lo = __shfl_sync(0xffffffffu, co[8][0], lid & ~3);
    float qz_hi = __shfl_sync(0xffffffffu, co[8][2], lid & ~3);
    float inv_lo = 1.f / (s_lo + qz_lo + EPSF);
    float inv_hi = 1.f / (s_hi + qz_hi + EPSF);

#pragma unroll
    for (int j = 0; j < 8; j++) {
        int col = h * HS + j * 8 + tq * 2;
        size_t i_lo = (size_t)(t0g + row_lo) * D_MODEL + col;
        size_t i_hi = (size_t)(t0g + row_hi) * D_MODEL + col;
        uint32_t hw, lw;
        split2(co[j][0] * inv_lo, co[j][1] * inv_lo, hw, lw);
        *(uint32_t*)(g_ah + i_lo) = hw;
        *(uint32_t*)(g_al + i_lo) = lw;
        split2(co[j][2] * inv_hi, co[j][3] * inv_hi, hw, lw);
        *(uint32_t*)(g_ah + i_hi) = hw;
        *(uint32_t*)(g_al + i_hi) = lw;
    }
}

// ---------------- launch ----------------
extern "C" void kernel_launch(void* const* d_in, const int* in_sizes, int n_in,
                              void* d_out, int out_size) {
    const float* x     = (const float*)d_in[0];
    const float* w_qkv = (const float*)d_in[1];
    const float* w_out = (const float*)d_in[2];
    float* out = (float*)d_out;

    __nv_bfloat16 *ah, *al, *b2h, *b2l;
    cudaGetSymbolAddress((void**)&ah,  g_ah);
    cudaGetSymbolAddress((void**)&al,  g_al);
    cudaGetSymbolAddress((void**)&b2h, g_b2h);
    cudaGetSymbolAddress((void**)&b2l, g_b2l);
    int8_t *xa0, *xa1, *wb0, *wb1;
    float *sa, *sbv;
    cudaGetSymbolAddress((void**)&xa0, g_xa0);
    cudaGetSymbolAddress((void**)&xa1, g_xa1);
    cudaGetSymbolAddress((void**)&wb0, g_wb0);
    cudaGetSymbolAddress((void**)&wb1, g_wb1);
    cudaGetSymbolAddress((void**)&sa,  g_sa);
    cudaGetSymbolAddress((void**)&sbv, g_sb);

    const int CHUNK_SMEM = 2 * CHUNK * HS * sizeof(float);
    cudaFuncSetAttribute(gemm_i8,    cudaFuncAttributeMaxDynamicSharedMemorySize, GSM8);
    cudaFuncSetAttribute(gemm_bf16s, cudaFuncAttributeMaxDynamicSharedMemorySize, GSM_TOTAL);
    cudaFuncSetAttribute(chunk_sums, cudaFuncAttributeMaxDynamicSharedMemorySize, CHUNK_SMEM);
    cudaFuncSetAttribute(attn_mma,   cudaFuncAttributeMaxDynamicSharedMemorySize, ATTN_SMEM_B);

    quant_rows<<<T_LEN, 256>>>(x, xa0, xa1, sa);
    quant_rows<<<3 * D_MODEL, 256>>>(w_qkv, wb0, wb1, sbv);
    splitk<<<(D_MODEL * D_MODEL / 4 + 255) / 256, 256>>>(w_out, b2h, b2l, D_MODEL * D_MODEL / 4);

    dim3 g1(3 * D_MODEL / 64, T_LEN / 64);     // (48, 32)
    gemm_i8<<<g1, 256, GSM8>>>();

    chunk_sums<<<H_NUM * NC, 256, CHUNK_SMEM>>>();
    chunk_prefix<<<H_NUM * 20, 256>>>();
    attn_mma<<<H_NUM * NC, 256, ATTN_SMEM_B>>>();

    dim3 g2(D_MODEL / 128, T_LEN / 128);       // (8, 16)
    gemm_bf16s<<<g2, 256, GSM_TOTAL>>>(ah, al, b2h, b2l, out, T_LEN, D_MODEL, D_MODEL);
}

// round 9
// speedup vs baseline: 2.6463x; 2.6463x over previous
#include <cuda_runtime.h>
#include <cuda_bf16.h>
#include <cuda_fp16.h>
#include <cstdint>

#define T_LEN 2048
#define D_MODEL 1024
#define H_NUM 16
#define HS 64
#define CHUNK 128
#define NC 16
#define EPSF 1e-6f
#define SCP 80

// ---------------- scratch ----------------
__device__ float g_Sc [H_NUM * NC * HS * SCP];
__device__ __align__(16) __nv_bfloat16 g_sph[H_NUM * NC * HS * SCP];
__device__ __align__(16) __nv_bfloat16 g_spl[H_NUM * NC * HS * SCP];

__device__ __align__(16) __nv_bfloat16 g_qkvh[3][H_NUM][T_LEN][HS];
__device__ __align__(16) __nv_bfloat16 g_qkvl[3][H_NUM][T_LEN][HS];

// fp16 GEMM operands: A limbs (x, then xo), weights single-limb
__device__ __align__(16) __half g_xh[T_LEN * D_MODEL];
__device__ __align__(16) __half g_xl[T_LEN * D_MODEL];
__device__ __align__(16) __half g_w1[3 * D_MODEL * D_MODEL];
__device__ __align__(16) __half g_w2[D_MODEL * D_MODEL];

__device__ __forceinline__ float phi(float x) {
    return x > 0.f ? x + 1.f : expf(x);
}
// bf16 split (attn chain)
__device__ __forceinline__ void split1(float x, __nv_bfloat16& h, __nv_bfloat16& l) {
    h = __float2bfloat16_rn(x);
    l = __float2bfloat16_rn(x - __bfloat162float(h));
}
__device__ __forceinline__ void split2(float a, float b, uint32_t& hi, uint32_t& lo) {
    __nv_bfloat16 ha, la, hb, lb;
    split1(a, ha, la);
    split1(b, hb, lb);
    hi = (uint32_t)__bfloat16_as_ushort(ha) | ((uint32_t)__bfloat16_as_ushort(hb) << 16);
    lo = (uint32_t)__bfloat16_as_ushort(la) | ((uint32_t)__bfloat16_as_ushort(lb) << 16);
}
// fp16 split (GEMM A side)
__device__ __forceinline__ void splitH2(float a, float b, uint32_t& hi, uint32_t& lo) {
    __half ha = __float2half_rn(a), hb = __float2half_rn(b);
    __half la = __float2half_rn(a - __half2float(ha));
    __half lb = __float2half_rn(b - __half2float(hb));
    hi = (uint32_t)__half_as_ushort(ha) | ((uint32_t)__half_as_ushort(hb) << 16);
    lo = (uint32_t)__half_as_ushort(la) | ((uint32_t)__half_as_ushort(lb) << 16);
}

// fp32 -> 2x fp16 limbs
__global__ __launch_bounds__(256) void splitkh(const float* __restrict__ s,
                                               __half* __restrict__ h,
                                               __half* __restrict__ l, int n4) {
    int i = blockIdx.x * 256 + threadIdx.x;
    if (i >= n4) return;
    float4 v = ((const float4*)s)[i];
    uint32_t h01, l01, h23, l23;
    splitH2(v.x, v.y, h01, l01);
    splitH2(v.z, v.w, h23, l23);
    ((uint2*)h)[i] = make_uint2(h01, h23);
    ((uint2*)l)[i] = make_uint2(l01, l23);
}
// fp32 -> 1x fp16
__global__ __launch_bounds__(256) void cvth(const float* __restrict__ s,
                                            __half* __restrict__ h, int n4) {
    int i = blockIdx.x * 256 + threadIdx.x;
    if (i >= n4) return;
    float4 v = ((const float4*)s)[i];
    uint32_t a = (uint32_t)__half_as_ushort(__float2half_rn(v.x)) |
                 ((uint32_t)__half_as_ushort(__float2half_rn(v.y)) << 16);
    uint32_t b = (uint32_t)__half_as_ushort(__float2half_rn(v.z)) |
                 ((uint32_t)__half_as_ushort(__float2half_rn(v.w)) << 16);
    ((uint2*)h)[i] = make_uint2(a, b);
}

// ---------------- mma helpers ----------------
__device__ __forceinline__ uint32_t smem_u32(const void* p) {
    uint32_t a;
    asm("{ .reg .u64 t; cvta.to.shared.u64 t, %1; cvt.u32.u64 %0, t; }" : "=r"(a) : "l"(p));
    return a;
}
__device__ __forceinline__ void ldsm4(uint32_t* r, uint32_t addr) {
    asm volatile("ldmatrix.sync.aligned.m8n8.x4.shared.b16 {%0,%1,%2,%3}, [%4];"
                 : "=r"(r[0]), "=r"(r[1]), "=r"(r[2]), "=r"(r[3]) : "r"(addr));
}
__device__ __forceinline__ void ldsm4t(uint32_t* r, uint32_t addr) {
    asm volatile("ldmatrix.sync.aligned.m8n8.x4.trans.shared.b16 {%0,%1,%2,%3}, [%4];"
                 : "=r"(r[0]), "=r"(r[1]), "=r"(r[2]), "=r"(r[3]) : "r"(addr));
}
__device__ __forceinline__ void mma16816(float* d, const uint32_t* a, const uint32_t* b) {
    asm volatile("mma.sync.aligned.m16n8k16.row.col.f32.bf16.bf16.f32 "
                 "{%0,%1,%2,%3},{%4,%5,%6,%7},{%8,%9},{%0,%1,%2,%3};"
                 : "+f"(d[0]), "+f"(d[1]), "+f"(d[2]), "+f"(d[3])
                 : "r"(a[0]), "r"(a[1]), "r"(a[2]), "r"(a[3]), "r"(b[0]), "r"(b[1]));
}
__device__ __forceinline__ void mmaf16(float* d, const uint32_t* a, const uint32_t* b) {
    asm volatile("mma.sync.aligned.m16n8k16.row.col.f32.f16.f16.f32 "
                 "{%0,%1,%2,%3},{%4,%5,%6,%7},{%8,%9},{%0,%1,%2,%3};"
                 : "+f"(d[0]), "+f"(d[1]), "+f"(d[2]), "+f"(d[3])
                 : "r"(a[0]), "r"(a[1]), "r"(a[2]), "r"(a[3]), "r"(b[0]), "r"(b[1]));
}
#define CP16(dst, src) \
    asm volatile("cp.async.cg.shared.global [%0], [%1], 16;" :: "r"(dst), "l"(src) : "memory")
#define CP_COMMIT() asm volatile("cp.async.commit_group;" ::: "memory")
#define CP_WAIT0()  asm volatile("cp.async.wait_group 0;" ::: "memory")

// ============================================================================
// 2-product fp16 GEMM: C = A[M][K] @ B[N][K]^T, A = Ah + Al (fp16 limbs),
// B = Bh (fp16). CTA 128x128, 8 warps 32x64, BK=32, double buffer, 2 CTA/SM.
// EPI=1: fused phi + bf16-split -> g_qkv{h,l}. EPI=0: fp32 C.
// ============================================================================
#define TPITCH 80
#define TILE_B (128 * TPITCH)            /* 10240 */
#define STG3 (3 * TILE_B)                /* 30720: Ah, Al, Bh */
#define GSMF (2 * STG3)                  /* 61440 */

template<int EPI>
__global__ __launch_bounds__(256, 2) void gemm_fp16s(
        const __half* __restrict__ Ah, const __half* __restrict__ Al,
        const __half* __restrict__ Bh,
        float* __restrict__ C, int M, int N, int K) {
    extern __shared__ char smem[];
    const uint32_t sb = smem_u32(smem);

    const int tid = threadIdx.x;
    const int wid = tid >> 5, lid = tid & 31;
    const int warp_m = wid & 3, warp_n = wid >> 2;
    const int m0 = blockIdx.y * 128, n0 = blockIdx.x * 128;
    const int NKB = K >> 5;

    const __half* srcs[3] = {Ah, Al, Bh};

    const int a_row  = lid & 15;
    const int a_koff = (lid >> 4) * 8;
    const int b_n    = (lid & 7) + ((lid >> 4) << 3);
    const int b_ko   = ((lid >> 3) & 1) * 8;
    const int g = lid >> 2, tg = lid & 3;

    float acc[2][8][4];
#pragma unroll
    for (int i = 0; i < 2; i++)
#pragma unroll
        for (int j = 0; j < 8; j++)
#pragma unroll
            for (int k = 0; k < 4; k++) acc[i][j][k] = 0.f;

    // loader: 1536 chunks of 16B per stage, 6 per thread
#pragma unroll
    for (int j = 0; j < 6; j++) {
        int chunkid = tid + j * 256;
        int tile = chunkid / 512;
        int within = chunkid & 511;
        int row = within >> 2, c = within & 3;
        int grow = (tile < 2 ? m0 : n0) + row;
        CP16(sb + tile * TILE_B + row * TPITCH + c * 16,
             srcs[tile] + (size_t)grow * K + c * 8);
    }
    CP_COMMIT();
    CP_WAIT0();
    __syncthreads();

#pragma unroll 1
    for (int kb = 0; kb < NKB; kb++) {
        const uint32_t stage = sb + (kb & 1) * STG3;

        if (kb + 1 < NKB) {
            const uint32_t nstage = sb + ((kb + 1) & 1) * STG3;
#pragma unroll
            for (int j = 0; j < 6; j++) {
                int chunkid = tid + j * 256;
                int tile = chunkid / 512;
                int within = chunkid & 511;
                int row = within >> 2, c = within & 3;
                int grow = (tile < 2 ? m0 : n0) + row;
                CP16(nstage + tile * TILE_B + row * TPITCH + c * 16,
                     srcs[tile] + (size_t)grow * K + (kb + 1) * 32 + c * 8);
            }
            CP_COMMIT();
        }

        const uint32_t tAh = stage;
        const uint32_t tAl = stage + TILE_B;
        const uint32_t tBh = stage + 2 * TILE_B;

#pragma unroll
        for (int ks = 0; ks < 2; ks++) {
            uint32_t a_h[2][4], a_l[2][4];
#pragma unroll
            for (int mt = 0; mt < 2; mt++) {
                uint32_t ao = (uint32_t)((warp_m * 32 + mt * 16 + a_row) * TPITCH +
                                         (ks * 16 + a_koff) * 2);
                ldsm4(a_h[mt], tAh + ao);
                ldsm4(a_l[mt], tAl + ao);
            }
            uint32_t bf[4][4];
#pragma unroll
            for (int ng = 0; ng < 4; ng++) {
                uint32_t bo = (uint32_t)((warp_n * 64 + ng * 16 + b_n) * TPITCH +
                                         (ks * 16 + b_ko) * 2);
                ldsm4(bf[ng], tBh + bo);
            }
            // product hh (16 mmas, distinct accs)
#pragma unroll
            for (int ng = 0; ng < 4; ng++)
#pragma unroll
                for (int mt = 0; mt < 2; mt++) {
                    mmaf16(acc[mt][ng * 2 + 0], a_h[mt], &bf[ng][0]);
                    mmaf16(acc[mt][ng * 2 + 1], a_h[mt], &bf[ng][2]);
                }
            // product lh
#pragma unroll
            for (int ng = 0; ng < 4; ng++)
#pragma unroll
                for (int mt = 0; mt < 2; mt++) {
                    mmaf16(acc[mt][ng * 2 + 0], a_l[mt], &bf[ng][0]);
                    mmaf16(acc[mt][ng * 2 + 1], a_l[mt], &bf[ng][2]);
                }
        }

        if (kb + 1 < NKB) CP_WAIT0();
        __syncthreads();
    }

    // ---- epilogue ----
    if (EPI) {
#pragma unroll
        for (int mt = 0; mt < 2; mt++) {
#pragma unroll
            for (int j = 0; j < 8; j++) {
                float* d = acc[mt][j];
                int n = n0 + warp_n * 64 + j * 8 + tg * 2;
                int sq = n >> 10, hh2 = (n >> 6) & 15, dd = n & 63;
                int r0 = m0 + warp_m * 32 + mt * 16 + g;
                float v0 = d[0], v1 = d[1], v2 = d[2], v3 = d[3];
                if (sq < 2) { v0 = phi(v0); v1 = phi(v1); v2 = phi(v2); v3 = phi(v3); }
                uint32_t hw, lw;
                split2(v0, v1, hw, lw);
                *(uint32_t*)&g_qkvh[sq][hh2][r0][dd] = hw;
                *(uint32_t*)&g_qkvl[sq][hh2][r0][dd] = lw;
                split2(v2, v3, hw, lw);
                *(uint32_t*)&g_qkvh[sq][hh2][r0 + 8][dd] = hw;
                *(uint32_t*)&g_qkvl[sq][hh2][r0 + 8][dd] = lw;
            }
        }
    } else {
#pragma unroll
        for (int mt = 0; mt < 2; mt++) {
#pragma unroll
            for (int j = 0; j < 8; j++) {
                float* d = acc[mt][j];
                int r0 = m0 + warp_m * 32 + mt * 16 + g;
                int col = n0 + warp_n * 64 + j * 8 + tg * 2;
                *(float2*)(C + (size_t)r0 * N + col)       = make_float2(d[0], d[1]);
                *(float2*)(C + (size_t)(r0 + 8) * N + col) = make_float2(d[2], d[3]);
            }
        }
    }
}

// ---------------- per-chunk KV sums ----------------
__global__ __launch_bounds__(256) void chunk_sums() {
    extern __shared__ float sm[];
    float* Ks = sm;
    float* Vs = sm + CHUNK * HS;
    int blk = blockIdx.x;
    int h = blk >> 4, cc = blk & 15;
    int t0 = cc * CHUNK;
    int tid = threadIdx.x;

    for (int i = tid; i < CHUNK * HS; i += 256) {
        int t = i >> 6, d = i & 63;
        Ks[i] = __bfloat162float(g_qkvh[1][h][t0 + t][d]) +
                __bfloat162float(g_qkvl[1][h][t0 + t][d]);
        Vs[i] = __bfloat162float(g_qkvh[2][h][t0 + t][d]) +
                __bfloat162float(g_qkvl[2][h][t0 + t][d]);
    }
    __syncthreads();

    int d0 = (tid >> 4) * 4, f0 = (tid & 15) * 4;
    float acc[4][4];
#pragma unroll
    for (int i = 0; i < 4; i++)
#pragma unroll
        for (int j = 0; j < 4; j++) acc[i][j] = 0.f;

    for (int t = 0; t < CHUNK; t++) {
        float4 k4 = *(const float4*)&Ks[t * HS + d0];
        float4 v4 = *(const float4*)&Vs[t * HS + f0];
        float kf[4] = {k4.x, k4.y, k4.z, k4.w};
        float vf[4] = {v4.x, v4.y, v4.z, v4.w};
#pragma unroll
        for (int i = 0; i < 4; i++)
#pragma unroll
            for (int j = 0; j < 4; j++)
                acc[i][j] = fmaf(kf[i], vf[j], acc[i][j]);
    }
    float* Sout = g_Sc + (size_t)blk * HS * SCP;
#pragma unroll
    for (int i = 0; i < 4; i++)
#pragma unroll
        for (int j = 0; j < 4; j++)
            Sout[(d0 + i) * SCP + f0 + j] = acc[i][j];

    if (tid < HS) {
        float z = 0.f;
        for (int t = 0; t < CHUNK; t++) z += Ks[t * HS + tid];
        Sout[tid * SCP + 64] = z;
    }
    for (int i = tid; i < HS * 15; i += 256) {
        int r = i / 15, c2 = 65 + i % 15;
        Sout[r * SCP + c2] = 0.f;
    }
}

// ---------------- exclusive prefix -> split bf16 Sp ----------------
__global__ __launch_bounds__(256) void chunk_prefix() {
    int h = blockIdx.x / 20;
    int e = (blockIdx.x % 20) * 256 + threadIdx.x;
    float run = 0.f;
#pragma unroll
    for (int c = 0; c < NC; c++) {
        size_t idx = (size_t)(h * NC + c) * (HS * SCP) + e;
        __nv_bfloat16 hh, ll;
        split1(run, hh, ll);
        g_sph[idx] = hh;
        g_spl[idx] = ll;
        run += g_Sc[idx];
    }
}

// ============================================================================
// attention per chunk (R6 core; output now fp16 limbs to g_xh/g_xl)
// ============================================================================
#define QVP 144
#define SPB 176
#define OFF_QH 0
#define OFF_QL (1 * 128 * QVP)
#define OFF_KH (2 * 128 * QVP)
#define OFF_KL (3 * 128 * QVP)
#define OFF_VH (4 * 128 * QVP)
#define OFF_VL (5 * 128 * QVP)
#define OFF_SPH (6 * 128 * QVP)
#define OFF_SPL (OFF_SPH + 64 * SPB)
#define ATTN_SMEM_B (OFF_SPL + 64 * SPB)

__global__ __launch_bounds__(256) void attn_mma() {
    extern __shared__ char smc[];
    const uint32_t sb = smem_u32(smc);

    const int blk = blockIdx.x;
    const int h = blk >> 4, cc = blk & 15;
    const int t0g = cc * CHUNK;
    const int tid = threadIdx.x;
    const int w = tid >> 5, lid = tid & 31;

#pragma unroll
    for (int j = 0; j < 24; j++) {
        int chunkid = tid + j * 256;
        int buf = chunkid >> 10;
        int within = chunkid & 1023;
        int row = within >> 3, c = within & 7;
        int sidx = buf >> 1;
        const __nv_bfloat16* srcp = (buf & 1) ? &g_qkvl[sidx][h][t0g + row][0]
                                              : &g_qkvh[sidx][h][t0g + row][0];
        CP16(sb + buf * (128 * QVP) + row * QVP + c * 16, srcp + c * 8);
    }
#pragma unroll
    for (int j = 0; j < 5; j++) {
        int chunkid = tid + j * 256;
        int buf = chunkid / 640;
        int within = chunkid % 640;
        int row = within / 10, c = within % 10;
        const __nv_bfloat16* srcp = (buf ? g_spl : g_sph) + (size_t)blk * (HS * SCP) + row * SCP + c * 8;
        CP16(sb + OFF_SPH + buf * (64 * SPB) + row * SPB + c * 16, srcp);
    }
    CP_COMMIT();
    CP_WAIT0();
    __syncthreads();

    const int a_row  = lid & 15;
    const int a_koff = (lid >> 4) * 8;
    const int b_n    = (lid & 7) + ((lid >> 4) << 3);
    const int b_ko   = ((lid >> 3) & 1) * 8;
    const int t_row  = lid & 15;
    const int t_col  = ((lid >> 4) << 3);
    const int g = lid >> 2, tq = lid & 3;

    float ca[16][4];
#pragma unroll
    for (int j = 0; j < 16; j++)
#pragma unroll
        for (int e = 0; e < 4; e++) ca[j][e] = 0.f;

#pragma unroll
    for (int ks = 0; ks < 4; ks++) {
        uint32_t aqh[4], aql[4];
        uint32_t ao = (uint32_t)((w * 16 + a_row) * QVP + (ks * 16 + a_koff) * 2);
        ldsm4(aqh, sb + OFF_QH + ao);
        ldsm4(aql, sb + OFF_QL + ao);
#pragma unroll
        for (int sg = 0; sg < 8; sg++) {
            uint32_t bo = (uint32_t)((sg * 16 + b_n) * QVP + (ks * 16 + b_ko) * 2);
            uint32_t bkh[4], bkl[4];
            ldsm4(bkh, sb + OFF_KH + bo);
            ldsm4(bkl, sb + OFF_KL + bo);
            mma16816(ca[sg * 2 + 0], aqh, &bkh[0]);
            mma16816(ca[sg * 2 + 1], aqh, &bkh[2]);
            mma16816(ca[sg * 2 + 0], aqh, &bkl[0]);
            mma16816(ca[sg * 2 + 1], aqh, &bkl[2]);
            mma16816(ca[sg * 2 + 0], aql, &bkh[0]);
            mma16816(ca[sg * 2 + 1], aql, &bkh[2]);
        }
    }

    const int row_lo = w * 16 + g, row_hi = row_lo + 8;
    float s_lo = 0.f, s_hi = 0.f;
#pragma unroll
    for (int j = 0; j < 16; j++) {
        int c0 = j * 8 + tq * 2;
        if (c0     > row_lo) ca[j][0] = 0.f;
        if (c0 + 1 > row_lo) ca[j][1] = 0.f;
        if (c0     > row_hi) ca[j][2] = 0.f;
        if (c0 + 1 > row_hi) ca[j][3] = 0.f;
        s_lo += ca[j][0] + ca[j][1];
        s_hi += ca[j][2] + ca[j][3];
    }
    s_lo += __shfl_xor_sync(0xffffffffu, s_lo, 1);
    s_lo += __shfl_xor_sync(0xffffffffu, s_lo, 2);
    s_hi += __shfl_xor_sync(0xffffffffu, s_hi, 1);
    s_hi += __shfl_xor_sync(0xffffffffu, s_hi, 2);

    float co[10][4];
#pragma unroll
    for (int j = 0; j < 10; j++)
#pragma unroll
        for (int e = 0; e < 4; e++) co[j][e] = 0.f;

#pragma unroll
    for (int ks2 = 0; ks2 < 8; ks2++) {
        uint32_t ahf[4], alf[4];
        split2(ca[ks2 * 2 + 0][0], ca[ks2 * 2 + 0][1], ahf[0], alf[0]);
        split2(ca[ks2 * 2 + 0][2], ca[ks2 * 2 + 0][3], ahf[1], alf[1]);
        split2(ca[ks2 * 2 + 1][0], ca[ks2 * 2 + 1][1], ahf[2], alf[2]);
        split2(ca[ks2 * 2 + 1][2], ca[ks2 * 2 + 1][3], ahf[3], alf[3]);
#pragma unroll
        for (int fg = 0; fg < 4; fg++) {
            uint32_t bo = (uint32_t)((ks2 * 16 + t_row) * QVP + (fg * 16 + t_col) * 2);
            uint32_t bvh[4], bvl[4];
            ldsm4t(bvh, sb + OFF_VH + bo);
            ldsm4t(bvl, sb + OFF_VL + bo);
            mma16816(co[fg * 2 + 0], ahf, &bvh[0]);
            mma16816(co[fg * 2 + 1], ahf, &bvh[2]);
            mma16816(co[fg * 2 + 0], ahf, &bvl[0]);
            mma16816(co[fg * 2 + 1], ahf, &bvl[2]);
            mma16816(co[fg * 2 + 0], alf, &bvh[0]);
            mma16816(co[fg * 2 + 1], alf, &bvh[2]);
        }
    }

#pragma unroll
    for (int ks = 0; ks < 4; ks++) {
        uint32_t aqh[4], aql[4];
        uint32_t ao = (uint32_t)((w * 16 + a_row) * QVP + (ks * 16 + a_koff) * 2);
        ldsm4(aqh, sb + OFF_QH + ao);
        ldsm4(aql, sb + OFF_QL + ao);
#pragma unroll
        for (int fg = 0; fg < 5; fg++) {
            uint32_t bo = (uint32_t)((ks * 16 + t_row) * SPB + (fg * 16 + t_col) * 2);
            uint32_t bsh[4], bsl[4];
            ldsm4t(bsh, sb + OFF_SPH + bo);
            ldsm4t(bsl, sb + OFF_SPL + bo);
            mma16816(co[fg * 2 + 0], aqh, &bsh[0]);
            mma16816(co[fg * 2 + 1], aqh, &bsh[2]);
            mma16816(co[fg * 2 + 0], aqh, &bsl[0]);
            mma16816(co[fg * 2 + 1], aqh, &bsl[2]);
            mma16816(co[fg * 2 + 0], aql, &bsh[0]);
            mma16816(co[fg * 2 + 1], aql, &bsh[2]);
        }
    }

    float qz_lo = __shfl_sync(0xffffffffu, co[8][0], lid & ~3);
    float qz_hi = __shfl_sync(0xffffffffu, co[8][2], lid & ~3);
    float inv_lo = 1.f / (s_lo + qz_lo + EPSF);
    float inv_hi = 1.f / (s_hi + qz_hi + EPSF);

    // write xo pre-split as fp16 limbs for GEMM2
#pragma unroll
    for (int j = 0; j < 8; j++) {
        int col = h * HS + j * 8 + tq * 2;
        size_t i_lo = (size_t)(t0g + row_lo) * D_MODEL + col;
        size_t i_hi = (size_t)(t0g + row_hi) * D_MODEL + col;
        uint32_t hw, lw;
        splitH2(co[j][0] * inv_lo, co[j][1] * inv_lo, hw, lw);
        *(uint32_t*)(g_xh + i_lo) = hw;
        *(uint32_t*)(g_xl + i_lo) = lw;
        splitH2(co[j][2] * inv_hi, co[j][3] * inv_hi, hw, lw);
        *(uint32_t*)(g_xh + i_hi) = hw;
        *(uint32_t*)(g_xl + i_hi) = lw;
    }
}

// ---------------- launch ----------------
extern "C" void kernel_launch(void* const* d_in, const int* in_sizes, int n_in,
                              void* d_out, int out_size) {
    const float* x     = (const float*)d_in[0];
    const float* w_qkv = (const float*)d_in[1];
    const float* w_out = (const float*)d_in[2];
    float* out = (float*)d_out;

    __half *xh, *xl, *w1, *w2;
    cudaGetSymbolAddress((void**)&xh, g_xh);
    cudaGetSymbolAddress((void**)&xl, g_xl);
    cudaGetSymbolAddress((void**)&w1, g_w1);
    cudaGetSymbolAddress((void**)&w2, g_w2);

    const int CHUNK_SMEM = 2 * CHUNK * HS * sizeof(float);
    cudaFuncSetAttribute(gemm_fp16s<1>, cudaFuncAttributeMaxDynamicSharedMemorySize, GSMF);
    cudaFuncSetAttribute(gemm_fp16s<0>, cudaFuncAttributeMaxDynamicSharedMemorySize, GSMF);
    cudaFuncSetAttribute(chunk_sums, cudaFuncAttributeMaxDynamicSharedMemorySize, CHUNK_SMEM);
    cudaFuncSetAttribute(attn_mma,   cudaFuncAttributeMaxDynamicSharedMemorySize, ATTN_SMEM_B);

    splitkh<<<(T_LEN * D_MODEL / 4 + 255) / 256, 256>>>(x, xh, xl, T_LEN * D_MODEL / 4);
    cvth<<<(3 * D_MODEL * D_MODEL / 4 + 255) / 256, 256>>>(w_qkv, w1, 3 * D_MODEL * D_MODEL / 4);
    cvth<<<(D_MODEL * D_MODEL / 4 + 255) / 256, 256>>>(w_out, w2, D_MODEL * D_MODEL / 4);

    // GEMM1: qkv = x @ w_qkv^T (fused phi + bf16-split epilogue)
    dim3 g1(3 * D_MODEL / 128, T_LEN / 128);   // (24, 16)
    gemm_fp16s<1><<<g1, 256, GSMF>>>(xh, xl, w1, nullptr, T_LEN, 3 * D_MODEL, D_MODEL);

    chunk_sums<<<H_NUM * NC, 256, CHUNK_SMEM>>>();
    chunk_prefix<<<H_NUM * 20, 256>>>();
    attn_mma<<<H_NUM * NC, 256, ATTN_SMEM_B>>>();   // writes xo fp16 limbs into xh/xl

    // GEMM2: out = xo @ w_out^T
    dim3 g2(D_MODEL / 128, T_LEN / 128);       // (8, 16)
    gemm_fp16s<0><<<g2, 256, GSMF>>>(xh, xl, w2, out, T_LEN, D_MODEL, D_MODEL);
}

// round 10
// speedup vs baseline: 3.9531x; 1.4938x over previous
#include <cuda_runtime.h>
#include <cuda_bf16.h>
#include <cuda_fp16.h>
#include <cstdint>

#define T_LEN 2048
#define D_MODEL 1024
#define H_NUM 16
#define HS 64
#define CHUNK 128
#define NC 16
#define EPSF 1e-6f
#define SCP 80

// ---------------- scratch ----------------
__device__ float g_Sc [H_NUM * NC * HS * SCP];
__device__ __align__(16) __nv_bfloat16 g_sph[H_NUM * NC * HS * SCP];
__device__ __align__(16) __nv_bfloat16 g_spl[H_NUM * NC * HS * SCP];

__device__ __align__(16) __nv_bfloat16 g_qkvh[3][H_NUM][T_LEN][HS];
__device__ __align__(16) __nv_bfloat16 g_qkvl[3][H_NUM][T_LEN][HS];

// fp16 GEMM operands
__device__ __align__(16) __half g_xh[T_LEN * D_MODEL];        // x, then xo
__device__ __align__(16) __half g_w1[3 * D_MODEL * D_MODEL];
__device__ __align__(16) __half g_w2[D_MODEL * D_MODEL];

__device__ __forceinline__ float phi(float x) {
    return x > 0.f ? x + 1.f : expf(x);
}
// bf16 split (attn chain)
__device__ __forceinline__ void split1(float x, __nv_bfloat16& h, __nv_bfloat16& l) {
    h = __float2bfloat16_rn(x);
    l = __float2bfloat16_rn(x - __bfloat162float(h));
}
__device__ __forceinline__ void split2(float a, float b, uint32_t& hi, uint32_t& lo) {
    __nv_bfloat16 ha, la, hb, lb;
    split1(a, ha, la);
    split1(b, hb, lb);
    hi = (uint32_t)__bfloat16_as_ushort(ha) | ((uint32_t)__bfloat16_as_ushort(hb) << 16);
    lo = (uint32_t)__bfloat16_as_ushort(la) | ((uint32_t)__bfloat16_as_ushort(lb) << 16);
}
__device__ __forceinline__ uint32_t packh2(float a, float b) {
    return (uint32_t)__half_as_ushort(__float2half_rn(a)) |
           ((uint32_t)__half_as_ushort(__float2half_rn(b)) << 16);
}

// fp32 -> fp16
__global__ __launch_bounds__(256) void cvth(const float* __restrict__ s,
                                            __half* __restrict__ h, int n4) {
    int i = blockIdx.x * 256 + threadIdx.x;
    if (i >= n4) return;
    float4 v = ((const float4*)s)[i];
    ((uint2*)h)[i] = make_uint2(packh2(v.x, v.y), packh2(v.z, v.w));
}

// ---------------- mma helpers ----------------
__device__ __forceinline__ uint32_t smem_u32(const void* p) {
    uint32_t a;
    asm("{ .reg .u64 t; cvta.to.shared.u64 t, %1; cvt.u32.u64 %0, t; }" : "=r"(a) : "l"(p));
    return a;
}
__device__ __forceinline__ void ldsm4(uint32_t* r, uint32_t addr) {
    asm volatile("ldmatrix.sync.aligned.m8n8.x4.shared.b16 {%0,%1,%2,%3}, [%4];"
                 : "=r"(r[0]), "=r"(r[1]), "=r"(r[2]), "=r"(r[3]) : "r"(addr));
}
__device__ __forceinline__ void ldsm4t(uint32_t* r, uint32_t addr) {
    asm volatile("ldmatrix.sync.aligned.m8n8.x4.trans.shared.b16 {%0,%1,%2,%3}, [%4];"
                 : "=r"(r[0]), "=r"(r[1]), "=r"(r[2]), "=r"(r[3]) : "r"(addr));
}
__device__ __forceinline__ void mma16816(float* d, const uint32_t* a, const uint32_t* b) {
    asm volatile("mma.sync.aligned.m16n8k16.row.col.f32.bf16.bf16.f32 "
                 "{%0,%1,%2,%3},{%4,%5,%6,%7},{%8,%9},{%0,%1,%2,%3};"
                 : "+f"(d[0]), "+f"(d[1]), "+f"(d[2]), "+f"(d[3])
                 : "r"(a[0]), "r"(a[1]), "r"(a[2]), "r"(a[3]), "r"(b[0]), "r"(b[1]));
}
__device__ __forceinline__ void mmaf16(float* d, const uint32_t* a, const uint32_t* b) {
    asm volatile("mma.sync.aligned.m16n8k16.row.col.f32.f16.f16.f32 "
                 "{%0,%1,%2,%3},{%4,%5,%6,%7},{%8,%9},{%0,%1,%2,%3};"
                 : "+f"(d[0]), "+f"(d[1]), "+f"(d[2]), "+f"(d[3])
                 : "r"(a[0]), "r"(a[1]), "r"(a[2]), "r"(a[3]), "r"(b[0]), "r"(b[1]));
}
#define CP16(dst, src) \
    asm volatile("cp.async.cg.shared.global [%0], [%1], 16;" :: "r"(dst), "l"(src) : "memory")
#define CP_COMMIT() asm volatile("cp.async.commit_group;" ::: "memory")
#define CP_WAIT0()  asm volatile("cp.async.wait_group 0;" ::: "memory")

// ============================================================================
// pure fp16 GEMM: C = A[M][K] @ B[N][K]^T. CTA 128x128, 8 warps 32x64,
// BK=64, double buffer, 2 CTA/SM. EPI=1: fused phi + bf16-split -> g_qkv.
// smem: [128 rows][64 fp16 (128B) + 16B pad] = 144B pitch.
// ============================================================================
#define FPITCH 144
#define FTILE (128 * FPITCH)             /* 18432 */
#define FSTAGE (2 * FTILE)               /* 36864: A, B */
#define GSMF (2 * FSTAGE)                /* 73728 */

template<int EPI>
__global__ __launch_bounds__(256, 2) void gemm_fp16(
        const __half* __restrict__ A, const __half* __restrict__ B,
        float* __restrict__ C, int M, int N, int K) {
    extern __shared__ char smem[];
    const uint32_t sb = smem_u32(smem);

    const int tid = threadIdx.x;
    const int wid = tid >> 5, lid = tid & 31;
    const int warp_m = wid & 3, warp_n = wid >> 2;
    const int m0 = blockIdx.y * 128, n0 = blockIdx.x * 128;
    const int NKB = K >> 6;

    const int a_row  = lid & 15;
    const int a_koff = (lid >> 4) * 8;              // elements
    const int b_n    = (lid & 7) + ((lid >> 4) << 3);
    const int b_ko   = ((lid >> 3) & 1) * 8;        // elements
    const int g = lid >> 2, tg = lid & 3;

    float acc[2][8][4];
#pragma unroll
    for (int i = 0; i < 2; i++)
#pragma unroll
        for (int j = 0; j < 8; j++)
#pragma unroll
            for (int k = 0; k < 4; k++) acc[i][j][k] = 0.f;

    // loader: 2048 chunks of 16B per stage (A:1024, B:1024), 8 per thread
#pragma unroll
    for (int j = 0; j < 8; j++) {
        int chunkid = tid + j * 256;
        int tile = chunkid >> 10;
        int within = chunkid & 1023;
        int row = within >> 3, c = within & 7;
        const __half* src = (tile ? B + (size_t)(n0 + row) * K
                                  : A + (size_t)(m0 + row) * K) + c * 8;
        CP16(sb + tile * FTILE + row * FPITCH + c * 16, src);
    }
    CP_COMMIT();
    CP_WAIT0();
    __syncthreads();

#pragma unroll 1
    for (int kb = 0; kb < NKB; kb++) {
        const uint32_t stage = sb + (kb & 1) * FSTAGE;

        if (kb + 1 < NKB) {
            const uint32_t nstage = sb + ((kb + 1) & 1) * FSTAGE;
#pragma unroll
            for (int j = 0; j < 8; j++) {
                int chunkid = tid + j * 256;
                int tile = chunkid >> 10;
                int within = chunkid & 1023;
                int row = within >> 3, c = within & 7;
                const __half* src = (tile ? B + (size_t)(n0 + row) * K
                                          : A + (size_t)(m0 + row) * K) +
                                    (kb + 1) * 64 + c * 8;
                CP16(nstage + tile * FTILE + row * FPITCH + c * 16, src);
            }
            CP_COMMIT();
        }

        const uint32_t tA = stage;
        const uint32_t tB = stage + FTILE;

#pragma unroll
        for (int ks = 0; ks < 4; ks++) {
            uint32_t af[2][4];
#pragma unroll
            for (int mt = 0; mt < 2; mt++) {
                uint32_t ao = (uint32_t)((warp_m * 32 + mt * 16 + a_row) * FPITCH +
                                         (ks * 16 + a_koff) * 2);
                ldsm4(af[mt], tA + ao);
            }
            uint32_t bf[4][4];
#pragma unroll
            for (int ng = 0; ng < 4; ng++) {
                uint32_t bo = (uint32_t)((warp_n * 64 + ng * 16 + b_n) * FPITCH +
                                         (ks * 16 + b_ko) * 2);
                ldsm4(bf[ng], tB + bo);
            }
#pragma unroll
            for (int ng = 0; ng < 4; ng++)
#pragma unroll
                for (int mt = 0; mt < 2; mt++) {
                    mmaf16(acc[mt][ng * 2 + 0], af[mt], &bf[ng][0]);
                    mmaf16(acc[mt][ng * 2 + 1], af[mt], &bf[ng][2]);
                }
        }

        if (kb + 1 < NKB) CP_WAIT0();
        __syncthreads();
    }

    // ---- epilogue ----
    if (EPI) {
#pragma unroll
        for (int mt = 0; mt < 2; mt++) {
#pragma unroll
            for (int j = 0; j < 8; j++) {
                float* d = acc[mt][j];
                int n = n0 + warp_n * 64 + j * 8 + tg * 2;
                int sq = n >> 10, hh2 = (n >> 6) & 15, dd = n & 63;
                int r0 = m0 + warp_m * 32 + mt * 16 + g;
                float v0 = d[0], v1 = d[1], v2 = d[2], v3 = d[3];
                if (sq < 2) { v0 = phi(v0); v1 = phi(v1); v2 = phi(v2); v3 = phi(v3); }
                uint32_t hw, lw;
                split2(v0, v1, hw, lw);
                *(uint32_t*)&g_qkvh[sq][hh2][r0][dd] = hw;
                *(uint32_t*)&g_qkvl[sq][hh2][r0][dd] = lw;
                split2(v2, v3, hw, lw);
                *(uint32_t*)&g_qkvh[sq][hh2][r0 + 8][dd] = hw;
                *(uint32_t*)&g_qkvl[sq][hh2][r0 + 8][dd] = lw;
            }
        }
    } else {
#pragma unroll
        for (int mt = 0; mt < 2; mt++) {
#pragma unroll
            for (int j = 0; j < 8; j++) {
                float* d = acc[mt][j];
                int r0 = m0 + warp_m * 32 + mt * 16 + g;
                int col = n0 + warp_n * 64 + j * 8 + tg * 2;
                *(float2*)(C + (size_t)r0 * N + col)       = make_float2(d[0], d[1]);
                *(float2*)(C + (size_t)(r0 + 8) * N + col) = make_float2(d[2], d[3]);
            }
        }
    }
}

// ---------------- per-chunk KV sums ----------------
__global__ __launch_bounds__(256) void chunk_sums() {
    extern __shared__ float sm[];
    float* Ks = sm;
    float* Vs = sm + CHUNK * HS;
    int blk = blockIdx.x;
    int h = blk >> 4, cc = blk & 15;
    int t0 = cc * CHUNK;
    int tid = threadIdx.x;

    for (int i = tid; i < CHUNK * HS; i += 256) {
        int t = i >> 6, d = i & 63;
        Ks[i] = __bfloat162float(g_qkvh[1][h][t0 + t][d]) +
                __bfloat162float(g_qkvl[1][h][t0 + t][d]);
        Vs[i] = __bfloat162float(g_qkvh[2][h][t0 + t][d]) +
                __bfloat162float(g_qkvl[2][h][t0 + t][d]);
    }
    __syncthreads();

    int d0 = (tid >> 4) * 4, f0 = (tid & 15) * 4;
    float acc[4][4];
#pragma unroll
    for (int i = 0; i < 4; i++)
#pragma unroll
        for (int j = 0; j < 4; j++) acc[i][j] = 0.f;

    for (int t = 0; t < CHUNK; t++) {
        float4 k4 = *(const float4*)&Ks[t * HS + d0];
        float4 v4 = *(const float4*)&Vs[t * HS + f0];
        float kf[4] = {k4.x, k4.y, k4.z, k4.w};
        float vf[4] = {v4.x, v4.y, v4.z, v4.w};
#pragma unroll
        for (int i = 0; i < 4; i++)
#pragma unroll
            for (int j = 0; j < 4; j++)
                acc[i][j] = fmaf(kf[i], vf[j], acc[i][j]);
    }
    float* Sout = g_Sc + (size_t)blk * HS * SCP;
#pragma unroll
    for (int i = 0; i < 4; i++)
#pragma unroll
        for (int j = 0; j < 4; j++)
            Sout[(d0 + i) * SCP + f0 + j] = acc[i][j];

    if (tid < HS) {
        float z = 0.f;
        for (int t = 0; t < CHUNK; t++) z += Ks[t * HS + tid];
        Sout[tid * SCP + 64] = z;
    }
    for (int i = tid; i < HS * 15; i += 256) {
        int r = i / 15, c2 = 65 + i % 15;
        Sout[r * SCP + c2] = 0.f;
    }
}

// ---------------- exclusive prefix -> split bf16 Sp ----------------
__global__ __launch_bounds__(256) void chunk_prefix() {
    int h = blockIdx.x / 20;
    int e = (blockIdx.x % 20) * 256 + threadIdx.x;
    float run = 0.f;
#pragma unroll
    for (int c = 0; c < NC; c++) {
        size_t idx = (size_t)(h * NC + c) * (HS * SCP) + e;
        __nv_bfloat16 hh, ll;
        split1(run, hh, ll);
        g_sph[idx] = hh;
        g_spl[idx] = ll;
        run += g_Sc[idx];
    }
}

// ============================================================================
// attention per chunk (bf16 3-product core; xo written as single fp16)
// ============================================================================
#define QVP 144
#define SPB 176
#define OFF_QH 0
#define OFF_QL (1 * 128 * QVP)
#define OFF_KH (2 * 128 * QVP)
#define OFF_KL (3 * 128 * QVP)
#define OFF_VH (4 * 128 * QVP)
#define OFF_VL (5 * 128 * QVP)
#define OFF_SPH (6 * 128 * QVP)
#define OFF_SPL (OFF_SPH + 64 * SPB)
#define ATTN_SMEM_B (OFF_SPL + 64 * SPB)

__global__ __launch_bounds__(256) void attn_mma() {
    extern __shared__ char smc[];
    const uint32_t sb = smem_u32(smc);

    const int blk = blockIdx.x;
    const int h = blk >> 4, cc = blk & 15;
    const int t0g = cc * CHUNK;
    const int tid = threadIdx.x;
    const int w = tid >> 5, lid = tid & 31;

#pragma unroll
    for (int j = 0; j < 24; j++) {
        int chunkid = tid + j * 256;
        int buf = chunkid >> 10;
        int within = chunkid & 1023;
        int row = within >> 3, c = within & 7;
        int sidx = buf >> 1;
        const __nv_bfloat16* srcp = (buf & 1) ? &g_qkvl[sidx][h][t0g + row][0]
                                              : &g_qkvh[sidx][h][t0g + row][0];
        CP16(sb + buf * (128 * QVP) + row * QVP + c * 16, srcp + c * 8);
    }
#pragma unroll
    for (int j = 0; j < 5; j++) {
        int chunkid = tid + j * 256;
        int buf = chunkid / 640;
        int within = chunkid % 640;
        int row = within / 10, c = within % 10;
        const __nv_bfloat16* srcp = (buf ? g_spl : g_sph) + (size_t)blk * (HS * SCP) + row * SCP + c * 8;
        CP16(sb + OFF_SPH + buf * (64 * SPB) + row * SPB + c * 16, srcp);
    }
    CP_COMMIT();
    CP_WAIT0();
    __syncthreads();

    const int a_row  = lid & 15;
    const int a_koff = (lid >> 4) * 8;
    const int b_n    = (lid & 7) + ((lid >> 4) << 3);
    const int b_ko   = ((lid >> 3) & 1) * 8;
    const int t_row  = lid & 15;
    const int t_col  = ((lid >> 4) << 3);
    const int g = lid >> 2, tq = lid & 3;

    float ca[16][4];
#pragma unroll
    for (int j = 0; j < 16; j++)
#pragma unroll
        for (int e = 0; e < 4; e++) ca[j][e] = 0.f;

#pragma unroll
    for (int ks = 0; ks < 4; ks++) {
        uint32_t aqh[4], aql[4];
        uint32_t ao = (uint32_t)((w * 16 + a_row) * QVP + (ks * 16 + a_koff) * 2);
        ldsm4(aqh, sb + OFF_QH + ao);
        ldsm4(aql, sb + OFF_QL + ao);
#pragma unroll
        for (int sg = 0; sg < 8; sg++) {
            uint32_t bo = (uint32_t)((sg * 16 + b_n) * QVP + (ks * 16 + b_ko) * 2);
            uint32_t bkh[4], bkl[4];
            ldsm4(bkh, sb + OFF_KH + bo);
            ldsm4(bkl, sb + OFF_KL + bo);
            mma16816(ca[sg * 2 + 0], aqh, &bkh[0]);
            mma16816(ca[sg * 2 + 1], aqh, &bkh[2]);
            mma16816(ca[sg * 2 + 0], aqh, &bkl[0]);
            mma16816(ca[sg * 2 + 1], aqh, &bkl[2]);
            mma16816(ca[sg * 2 + 0], aql, &bkh[0]);
            mma16816(ca[sg * 2 + 1], aql, &bkh[2]);
        }
    }

    const int row_lo = w * 16 + g, row_hi = row_lo + 8;
    float s_lo = 0.f, s_hi = 0.f;
#pragma unroll
    for (int j = 0; j < 16; j++) {
        int c0 = j * 8 + tq * 2;
        if (c0     > row_lo) ca[j][0] = 0.f;
        if (c0 + 1 > row_lo) ca[j][1] = 0.f;
        if (c0     > row_hi) ca[j][2] = 0.f;
        if (c0 + 1 > row_hi) ca[j][3] = 0.f;
        s_lo += ca[j][0] + ca[j][1];
        s_hi += ca[j][2] + ca[j][3];
    }
    s_lo += __shfl_xor_sync(0xffffffffu, s_lo, 1);
    s_lo += __shfl_xor_sync(0xffffffffu, s_lo, 2);
    s_hi += __shfl_xor_sync(0xffffffffu, s_hi, 1);
    s_hi += __shfl_xor_sync(0xffffffffu, s_hi, 2);

    float co[10][4];
#pragma unroll
    for (int j = 0; j < 10; j++)
#pragma unroll
        for (int e = 0; e < 4; e++) co[j][e] = 0.f;

#pragma unroll
    for (int ks2 = 0; ks2 < 8; ks2++) {
        uint32_t ahf[4], alf[4];
        split2(ca[ks2 * 2 + 0][0], ca[ks2 * 2 + 0][1], ahf[0], alf[0]);
        split2(ca[ks2 * 2 + 0][2], ca[ks2 * 2 + 0][3], ahf[1], alf[1]);
        split2(ca[ks2 * 2 + 1][0], ca[ks2 * 2 + 1][1], ahf[2], alf[2]);
        split2(ca[ks2 * 2 + 1][2], ca[ks2 * 2 + 1][3], ahf[3], alf[3]);
#pragma unroll
        for (int fg = 0; fg < 4; fg++) {
            uint32_t bo = (uint32_t)((ks2 * 16 + t_row) * QVP + (fg * 16 + t_col) * 2);
            uint32_t bvh[4], bvl[4];
            ldsm4t(bvh, sb + OFF_VH + bo);
            ldsm4t(bvl, sb + OFF_VL + bo);
            mma16816(co[fg * 2 + 0], ahf, &bvh[0]);
            mma16816(co[fg * 2 + 1], ahf, &bvh[2]);
            mma16816(co[fg * 2 + 0], ahf, &bvl[0]);
            mma16816(co[fg * 2 + 1], ahf, &bvl[2]);
            mma16816(co[fg * 2 + 0], alf, &bvh[0]);
            mma16816(co[fg * 2 + 1], alf, &bvh[2]);
        }
    }

#pragma unroll
    for (int ks = 0; ks < 4; ks++) {
        uint32_t aqh[4], aql[4];
        uint32_t ao = (uint32_t)((w * 16 + a_row) * QVP + (ks * 16 + a_koff) * 2);
        ldsm4(aqh, sb + OFF_QH + ao);
        ldsm4(aql, sb + OFF_QL + ao);
#pragma unroll
        for (int fg = 0; fg < 5; fg++) {
            uint32_t bo = (uint32_t)((ks * 16 + t_row) * SPB + (fg * 16 + t_col) * 2);
            uint32_t bsh[4], bsl[4];
            ldsm4t(bsh, sb + OFF_SPH + bo);
            ldsm4t(bsl, sb + OFF_SPL + bo);
            mma16816(co[fg * 2 + 0], aqh, &bsh[0]);
            mma16816(co[fg * 2 + 1], aqh, &bsh[2]);
            mma16816(co[fg * 2 + 0], aqh, &bsl[0]);
            mma16816(co[fg * 2 + 1], aqh, &bsl[2]);
            mma16816(co[fg * 2 + 0], aql, &bsh[0]);
            mma16816(co[fg * 2 + 1], aql, &bsh[2]);
        }
    }

    float qz_lo = __shfl_sync(0xffffffffu, co[8][0], lid & ~3);
    float qz_hi = __shfl_sync(0xffffffffu, co[8][2], lid & ~3);
    float inv_lo = 1.f / (s_lo + qz_lo + EPSF);
    float inv_hi = 1.f / (s_hi + qz_hi + EPSF);

    // write xo as single fp16 for GEMM2
#pragma unroll
    for (int j = 0; j < 8; j++) {
        int col = h * HS + j * 8 + tq * 2;
        size_t i_lo = (size_t)(t0g + row_lo) * D_MODEL + col;
        size_t i_hi = (size_t)(t0g + row_hi) * D_MODEL + col;
        *(uint32_t*)(g_xh + i_lo) = packh2(co[j][0] * inv_lo, co[j][1] * inv_lo);
        *(uint32_t*)(g_xh + i_hi) = packh2(co[j][2] * inv_hi, co[j][3] * inv_hi);
    }
}

// ---------------- launch ----------------
extern "C" void kernel_launch(void* const* d_in, const int* in_sizes, int n_in,
                              void* d_out, int out_size) {
    const float* x     = (const float*)d_in[0];
    const float* w_qkv = (const float*)d_in[1];
    const float* w_out = (const float*)d_in[2];
    float* out = (float*)d_out;

    __half *xh, *w1, *w2;
    cudaGetSymbolAddress((void**)&xh, g_xh);
    cudaGetSymbolAddress((void**)&w1, g_w1);
    cudaGetSymbolAddress((void**)&w2, g_w2);

    const int CHUNK_SMEM = 2 * CHUNK * HS * sizeof(float);
    cudaFuncSetAttribute(gemm_fp16<1>, cudaFuncAttributeMaxDynamicSharedMemorySize, GSMF);
    cudaFuncSetAttribute(gemm_fp16<0>, cudaFuncAttributeMaxDynamicSharedMemorySize, GSMF);
    cudaFuncSetAttribute(chunk_sums, cudaFuncAttributeMaxDynamicSharedMemorySize, CHUNK_SMEM);
    cudaFuncSetAttribute(attn_mma,   cudaFuncAttributeMaxDynamicSharedMemorySize, ATTN_SMEM_B);

    cvth<<<(T_LEN * D_MODEL / 4 + 255) / 256, 256>>>(x, xh, T_LEN * D_MODEL / 4);
    cvth<<<(3 * D_MODEL * D_MODEL / 4 + 255) / 256, 256>>>(w_qkv, w1, 3 * D_MODEL * D_MODEL / 4);
    cvth<<<(D_MODEL * D_MODEL / 4 + 255) / 256, 256>>>(w_out, w2, D_MODEL * D_MODEL / 4);

    // GEMM1: qkv = x @ w_qkv^T (fused phi + bf16-split epilogue)
    dim3 g1(3 * D_MODEL / 128, T_LEN / 128);   // (24, 16)
    gemm_fp16<1><<<g1, 256, GSMF>>>(xh, w1, nullptr, T_LEN, 3 * D_MODEL, D_MODEL);

    chunk_sums<<<H_NUM * NC, 256, CHUNK_SMEM>>>();
    chunk_prefix<<<H_NUM * 20, 256>>>();
    attn_mma<<<H_NUM * NC, 256, ATTN_SMEM_B>>>();   // writes xo fp16 into xh

    // GEMM2: out = xo @ w_out^T
    dim3 g2(D_MODEL / 128, T_LEN / 128);       // (8, 16)
    gemm_fp16<0><<<g2, 256, GSMF>>>(xh, w2, out, T_LEN, D_MODEL, D_MODEL);
}

// round 11
// speedup vs baseline: 4.4149x; 1.1168x over previous
#include <cuda_runtime.h>
#include <cuda_bf16.h>
#include <cuda_fp16.h>
#include <cstdint>

#define T_LEN 2048
#define D_MODEL 1024
#define H_NUM 16
#define HS 64
#define CHUNK 128
#define NC 16
#define EPSF 1e-6f
#define SCP 80

// ---------------- scratch ----------------
__device__ float g_Sc [H_NUM * NC * HS * SCP];
__device__ __align__(16) __half g_sp[H_NUM * NC * HS * SCP];     // prefix, fp16

__device__ __align__(16) __half g_qkv[3][H_NUM][T_LEN][HS];      // phi(q),phi(k),v fp16

__device__ __align__(16) __half g_xh[T_LEN * D_MODEL];           // x, then xo
__device__ __align__(16) __half g_w1[3 * D_MODEL * D_MODEL];
__device__ __align__(16) __half g_w2[D_MODEL * D_MODEL];

__device__ __forceinline__ float phi(float x) {
    return x > 0.f ? x + 1.f : expf(x);
}
__device__ __forceinline__ uint32_t packh2(float a, float b) {
    return (uint32_t)__half_as_ushort(__float2half_rn(a)) |
           ((uint32_t)__half_as_ushort(__float2half_rn(b)) << 16);
}

// fp32 -> fp16
__global__ __launch_bounds__(256) void cvth(const float* __restrict__ s,
                                            __half* __restrict__ h, int n4) {
    int i = blockIdx.x * 256 + threadIdx.x;
    if (i >= n4) return;
    float4 v = ((const float4*)s)[i];
    ((uint2*)h)[i] = make_uint2(packh2(v.x, v.y), packh2(v.z, v.w));
}

// ---------------- mma helpers ----------------
__device__ __forceinline__ uint32_t smem_u32(const void* p) {
    uint32_t a;
    asm("{ .reg .u64 t; cvta.to.shared.u64 t, %1; cvt.u32.u64 %0, t; }" : "=r"(a) : "l"(p));
    return a;
}
__device__ __forceinline__ void ldsm4(uint32_t* r, uint32_t addr) {
    asm volatile("ldmatrix.sync.aligned.m8n8.x4.shared.b16 {%0,%1,%2,%3}, [%4];"
                 : "=r"(r[0]), "=r"(r[1]), "=r"(r[2]), "=r"(r[3]) : "r"(addr));
}
__device__ __forceinline__ void ldsm4t(uint32_t* r, uint32_t addr) {
    asm volatile("ldmatrix.sync.aligned.m8n8.x4.trans.shared.b16 {%0,%1,%2,%3}, [%4];"
                 : "=r"(r[0]), "=r"(r[1]), "=r"(r[2]), "=r"(r[3]) : "r"(addr));
}
__device__ __forceinline__ void mmaf16(float* d, const uint32_t* a, const uint32_t* b) {
    asm volatile("mma.sync.aligned.m16n8k16.row.col.f32.f16.f16.f32 "
                 "{%0,%1,%2,%3},{%4,%5,%6,%7},{%8,%9},{%0,%1,%2,%3};"
                 : "+f"(d[0]), "+f"(d[1]), "+f"(d[2]), "+f"(d[3])
                 : "r"(a[0]), "r"(a[1]), "r"(a[2]), "r"(a[3]), "r"(b[0]), "r"(b[1]));
}
#define CP16(dst, src) \
    asm volatile("cp.async.cg.shared.global [%0], [%1], 16;" :: "r"(dst), "l"(src) : "memory")
#define CP_COMMIT() asm volatile("cp.async.commit_group;" ::: "memory")
#define CP_WAIT0()  asm volatile("cp.async.wait_group 0;" ::: "memory")

// ============================================================================
// GEMM1: fp16, CTA 128x128, 8 warps 32x64, BK=64, double buffer, 2 CTA/SM.
// EPI=1: fused phi + fp16 store -> g_qkv. EPI=0: fp32 C.
// ============================================================================
#define FPITCH 144
#define FTILE (128 * FPITCH)             /* 18432 */
#define FSTAGE (2 * FTILE)               /* 36864 */
#define GSMF (2 * FSTAGE)                /* 73728 */

template<int EPI>
__global__ __launch_bounds__(256, 2) void gemm_fp16(
        const __half* __restrict__ A, const __half* __restrict__ B,
        float* __restrict__ C, int M, int N, int K) {
    extern __shared__ char smem[];
    const uint32_t sb = smem_u32(smem);

    const int tid = threadIdx.x;
    const int wid = tid >> 5, lid = tid & 31;
    const int warp_m = wid & 3, warp_n = wid >> 2;
    const int m0 = blockIdx.y * 128, n0 = blockIdx.x * 128;
    const int NKB = K >> 6;

    const int a_row  = lid & 15;
    const int a_koff = (lid >> 4) * 8;
    const int b_n    = (lid & 7) + ((lid >> 4) << 3);
    const int b_ko   = ((lid >> 3) & 1) * 8;
    const int g = lid >> 2, tg = lid & 3;

    float acc[2][8][4];
#pragma unroll
    for (int i = 0; i < 2; i++)
#pragma unroll
        for (int j = 0; j < 8; j++)
#pragma unroll
            for (int k = 0; k < 4; k++) acc[i][j][k] = 0.f;

#pragma unroll
    for (int j = 0; j < 8; j++) {
        int chunkid = tid + j * 256;
        int tile = chunkid >> 10;
        int within = chunkid & 1023;
        int row = within >> 3, c = within & 7;
        const __half* src = (tile ? B + (size_t)(n0 + row) * K
                                  : A + (size_t)(m0 + row) * K) + c * 8;
        CP16(sb + tile * FTILE + row * FPITCH + c * 16, src);
    }
    CP_COMMIT();
    CP_WAIT0();
    __syncthreads();

#pragma unroll 1
    for (int kb = 0; kb < NKB; kb++) {
        const uint32_t stage = sb + (kb & 1) * FSTAGE;

        if (kb + 1 < NKB) {
            const uint32_t nstage = sb + ((kb + 1) & 1) * FSTAGE;
#pragma unroll
            for (int j = 0; j < 8; j++) {
                int chunkid = tid + j * 256;
                int tile = chunkid >> 10;
                int within = chunkid & 1023;
                int row = within >> 3, c = within & 7;
                const __half* src = (tile ? B + (size_t)(n0 + row) * K
                                          : A + (size_t)(m0 + row) * K) +
                                    (kb + 1) * 64 + c * 8;
                CP16(nstage + tile * FTILE + row * FPITCH + c * 16, src);
            }
            CP_COMMIT();
        }

        const uint32_t tA = stage;
        const uint32_t tB = stage + FTILE;

#pragma unroll
        for (int ks = 0; ks < 4; ks++) {
            uint32_t af[2][4];
#pragma unroll
            for (int mt = 0; mt < 2; mt++) {
                uint32_t ao = (uint32_t)((warp_m * 32 + mt * 16 + a_row) * FPITCH +
                                         (ks * 16 + a_koff) * 2);
                ldsm4(af[mt], tA + ao);
            }
            uint32_t bf[4][4];
#pragma unroll
            for (int ng = 0; ng < 4; ng++) {
                uint32_t bo = (uint32_t)((warp_n * 64 + ng * 16 + b_n) * FPITCH +
                                         (ks * 16 + b_ko) * 2);
                ldsm4(bf[ng], tB + bo);
            }
#pragma unroll
            for (int ng = 0; ng < 4; ng++)
#pragma unroll
                for (int mt = 0; mt < 2; mt++) {
                    mmaf16(acc[mt][ng * 2 + 0], af[mt], &bf[ng][0]);
                    mmaf16(acc[mt][ng * 2 + 1], af[mt], &bf[ng][2]);
                }
        }

        if (kb + 1 < NKB) CP_WAIT0();
        __syncthreads();
    }

    if (EPI) {
#pragma unroll
        for (int mt = 0; mt < 2; mt++) {
#pragma unroll
            for (int j = 0; j < 8; j++) {
                float* d = acc[mt][j];
                int n = n0 + warp_n * 64 + j * 8 + tg * 2;
                int sq = n >> 10, hh2 = (n >> 6) & 15, dd = n & 63;
                int r0 = m0 + warp_m * 32 + mt * 16 + g;
                float v0 = d[0], v1 = d[1], v2 = d[2], v3 = d[3];
                if (sq < 2) { v0 = phi(v0); v1 = phi(v1); v2 = phi(v2); v3 = phi(v3); }
                *(uint32_t*)&g_qkv[sq][hh2][r0][dd]     = packh2(v0, v1);
                *(uint32_t*)&g_qkv[sq][hh2][r0 + 8][dd] = packh2(v2, v3);
            }
        }
    } else {
#pragma unroll
        for (int mt = 0; mt < 2; mt++) {
#pragma unroll
            for (int j = 0; j < 8; j++) {
                float* d = acc[mt][j];
                int r0 = m0 + warp_m * 32 + mt * 16 + g;
                int col = n0 + warp_n * 64 + j * 8 + tg * 2;
                *(float2*)(C + (size_t)r0 * N + col)       = make_float2(d[0], d[1]);
                *(float2*)(C + (size_t)(r0 + 8) * N + col) = make_float2(d[2], d[3]);
            }
        }
    }
}

// ============================================================================
// GEMM2: fp16, CTA 64x128 (256 CTAs -> 2/SM), 8 warps 32x32, BK=64.
// ============================================================================
#define G2A (64 * FPITCH)                /* 9216 */
#define G2B (128 * FPITCH)               /* 18432 */
#define G2STG (G2A + G2B)                /* 27648 */
#define GSM2 (2 * G2STG)                 /* 55296 */

__global__ __launch_bounds__(256, 2) void gemm2_fp16(
        const __half* __restrict__ A, const __half* __restrict__ B,
        float* __restrict__ C, int M, int N, int K) {
    extern __shared__ char smem[];
    const uint32_t sb = smem_u32(smem);

    const int tid = threadIdx.x;
    const int wid = tid >> 5, lid = tid & 31;
    const int warp_m = wid & 1, warp_n = wid >> 1;   // 2 x 4
    const int m0 = blockIdx.y * 64, n0 = blockIdx.x * 128;
    const int NKB = K >> 6;

    const int a_row  = lid & 15;
    const int a_koff = (lid >> 4) * 8;
    const int b_n    = (lid & 7) + ((lid >> 4) << 3);
    const int b_ko   = ((lid >> 3) & 1) * 8;
    const int g = lid >> 2, tg = lid & 3;

    float acc[2][4][4];
#pragma unroll
    for (int i = 0; i < 2; i++)
#pragma unroll
        for (int j = 0; j < 4; j++)
#pragma unroll
            for (int k = 0; k < 4; k++) acc[i][j][k] = 0.f;

    auto load_stage = [&](uint32_t stg, int kb) {
#pragma unroll
        for (int j = 0; j < 6; j++) {
            int chunkid = tid + j * 256;               // 0..1535
            if (chunkid < 512) {
                int row = chunkid >> 3, c = chunkid & 7;
                CP16(stg + row * FPITCH + c * 16,
                     A + (size_t)(m0 + row) * K + kb * 64 + c * 8);
            } else {
                int cid = chunkid - 512;
                int row = cid >> 3, c = cid & 7;
                CP16(stg + G2A + row * FPITCH + c * 16,
                     B + (size_t)(n0 + row) * K + kb * 64 + c * 8);
            }
        }
        CP_COMMIT();
    };

    load_stage(sb, 0);
    CP_WAIT0();
    __syncthreads();

#pragma unroll 1
    for (int kb = 0; kb < NKB; kb++) {
        const uint32_t stage = sb + (kb & 1) * G2STG;
        if (kb + 1 < NKB) load_stage(sb + ((kb + 1) & 1) * G2STG, kb + 1);

#pragma unroll
        for (int ks = 0; ks < 4; ks++) {
            uint32_t af[2][4];
#pragma unroll
            for (int mt = 0; mt < 2; mt++) {
                uint32_t ao = (uint32_t)((warp_m * 32 + mt * 16 + a_row) * FPITCH +
                                         (ks * 16 + a_koff) * 2);
                ldsm4(af[mt], stage + ao);
            }
            uint32_t bf[2][4];
#pragma unroll
            for (int nh = 0; nh < 2; nh++) {
                uint32_t bo = (uint32_t)((warp_n * 32 + nh * 16 + b_n) * FPITCH +
                                         (ks * 16 + b_ko) * 2);
                ldsm4(bf[nh], stage + G2A + bo);
            }
#pragma unroll
            for (int nh = 0; nh < 2; nh++)
#pragma unroll
                for (int mt = 0; mt < 2; mt++) {
                    mmaf16(acc[mt][nh * 2 + 0], af[mt], &bf[nh][0]);
                    mmaf16(acc[mt][nh * 2 + 1], af[mt], &bf[nh][2]);
                }
        }

        if (kb + 1 < NKB) CP_WAIT0();
        __syncthreads();
    }

#pragma unroll
    for (int mt = 0; mt < 2; mt++) {
#pragma unroll
        for (int j = 0; j < 4; j++) {
            float* d = acc[mt][j];
            int r0 = m0 + warp_m * 32 + mt * 16 + g;
            int col = n0 + warp_n * 32 + j * 8 + tg * 2;
            *(float2*)(C + (size_t)r0 * N + col)       = make_float2(d[0], d[1]);
            *(float2*)(C + (size_t)(r0 + 8) * N + col) = make_float2(d[2], d[3]);
        }
    }
}

// ---------------- per-chunk KV sums (reads fp16 qkv) ----------------
__global__ __launch_bounds__(256) void chunk_sums() {
    extern __shared__ float sm[];
    float* Ks = sm;
    float* Vs = sm + CHUNK * HS;
    int blk = blockIdx.x;
    int h = blk >> 4, cc = blk & 15;
    int t0 = cc * CHUNK;
    int tid = threadIdx.x;

    for (int i = tid; i < CHUNK * HS; i += 256) {
        int t = i >> 6, d = i & 63;
        Ks[i] = __half2float(g_qkv[1][h][t0 + t][d]);
        Vs[i] = __half2float(g_qkv[2][h][t0 + t][d]);
    }
    __syncthreads();

    int d0 = (tid >> 4) * 4, f0 = (tid & 15) * 4;
    float acc[4][4];
#pragma unroll
    for (int i = 0; i < 4; i++)
#pragma unroll
        for (int j = 0; j < 4; j++) acc[i][j] = 0.f;

    for (int t = 0; t < CHUNK; t++) {
        float4 k4 = *(const float4*)&Ks[t * HS + d0];
        float4 v4 = *(const float4*)&Vs[t * HS + f0];
        float kf[4] = {k4.x, k4.y, k4.z, k4.w};
        float vf[4] = {v4.x, v4.y, v4.z, v4.w};
#pragma unroll
        for (int i = 0; i < 4; i++)
#pragma unroll
            for (int j = 0; j < 4; j++)
                acc[i][j] = fmaf(kf[i], vf[j], acc[i][j]);
    }
    float* Sout = g_Sc + (size_t)blk * HS * SCP;
#pragma unroll
    for (int i = 0; i < 4; i++)
#pragma unroll
        for (int j = 0; j < 4; j++)
            Sout[(d0 + i) * SCP + f0 + j] = acc[i][j];

    if (tid < HS) {
        float z = 0.f;
        for (int t = 0; t < CHUNK; t++) z += Ks[t * HS + tid];
        Sout[tid * SCP + 64] = z;
    }
    for (int i = tid; i < HS * 15; i += 256) {
        int r = i / 15, c2 = 65 + i % 15;
        Sout[r * SCP + c2] = 0.f;
    }
}

// ---------------- exclusive prefix -> fp16 Sp ----------------
__global__ __launch_bounds__(256) void chunk_prefix() {
    int h = blockIdx.x / 20;
    int e = (blockIdx.x % 20) * 256 + threadIdx.x;
    float run = 0.f;
#pragma unroll
    for (int c = 0; c < NC; c++) {
        size_t idx = (size_t)(h * NC + c) * (HS * SCP) + e;
        g_sp[idx] = __float2half_rn(run);
        run += g_Sc[idx];
    }
}

// ============================================================================
// attention per chunk, single-limb fp16 mma throughout.
// smem: Q,K,V [128][72] fp16 (144B pitch); Sp [64][88] (176B pitch)
// ============================================================================
#define QVP 144
#define SPB 176
#define OFF_Q 0
#define OFF_K (1 * 128 * QVP)
#define OFF_V (2 * 128 * QVP)
#define OFF_SP (3 * 128 * QVP)
#define ATTN_SMEM_B (OFF_SP + 64 * SPB)   /* 66560 */

__global__ __launch_bounds__(256, 2) void attn_mma() {
    extern __shared__ char smc[];
    const uint32_t sb = smem_u32(smc);

    const int blk = blockIdx.x;
    const int h = blk >> 4, cc = blk & 15;
    const int t0g = cc * CHUNK;
    const int tid = threadIdx.x;
    const int w = tid >> 5, lid = tid & 31;

    // ---- async loads: q,k,v (3 x 128 rows x 8 chunks) + sp (640 chunks) ----
#pragma unroll
    for (int j = 0; j < 12; j++) {
        int chunkid = tid + j * 256;
        int buf = chunkid >> 10;
        int within = chunkid & 1023;
        int row = within >> 3, c = within & 7;
        CP16(sb + buf * (128 * QVP) + row * QVP + c * 16,
             &g_qkv[buf][h][t0g + row][0] + c * 8);
    }
#pragma unroll
    for (int j = 0; j < 3; j++) {
        int chunkid = tid + j * 256;
        if (chunkid < 640) {
            int row = chunkid / 10, c = chunkid % 10;
            CP16(sb + OFF_SP + row * SPB + c * 16,
                 g_sp + (size_t)blk * (HS * SCP) + row * SCP + c * 8);
        }
    }
    CP_COMMIT();
    CP_WAIT0();
    __syncthreads();

    const int a_row  = lid & 15;
    const int a_koff = (lid >> 4) * 8;
    const int b_n    = (lid & 7) + ((lid >> 4) << 3);
    const int b_ko   = ((lid >> 3) & 1) * 8;
    const int t_row  = lid & 15;
    const int t_col  = ((lid >> 4) << 3);
    const int g = lid >> 2, tq = lid & 3;

    // ---- step 1: A = Q K^T ----
    float ca[16][4];
#pragma unroll
    for (int j = 0; j < 16; j++)
#pragma unroll
        for (int e = 0; e < 4; e++) ca[j][e] = 0.f;

#pragma unroll
    for (int ks = 0; ks < 4; ks++) {
        uint32_t aq[4];
        ldsm4(aq, sb + OFF_Q + (uint32_t)((w * 16 + a_row) * QVP + (ks * 16 + a_koff) * 2));
#pragma unroll
        for (int sg = 0; sg < 8; sg++) {
            uint32_t bk[4];
            ldsm4(bk, sb + OFF_K + (uint32_t)((sg * 16 + b_n) * QVP + (ks * 16 + b_ko) * 2));
            mmaf16(ca[sg * 2 + 0], aq, &bk[0]);
            mmaf16(ca[sg * 2 + 1], aq, &bk[2]);
        }
    }

    // ---- step 2: causal mask + rowsum ----
    const int row_lo = w * 16 + g, row_hi = row_lo + 8;
    float s_lo = 0.f, s_hi = 0.f;
#pragma unroll
    for (int j = 0; j < 16; j++) {
        int c0 = j * 8 + tq * 2;
        if (c0     > row_lo) ca[j][0] = 0.f;
        if (c0 + 1 > row_lo) ca[j][1] = 0.f;
        if (c0     > row_hi) ca[j][2] = 0.f;
        if (c0 + 1 > row_hi) ca[j][3] = 0.f;
        s_lo += ca[j][0] + ca[j][1];
        s_hi += ca[j][2] + ca[j][3];
    }
    s_lo += __shfl_xor_sync(0xffffffffu, s_lo, 1);
    s_lo += __shfl_xor_sync(0xffffffffu, s_lo, 2);
    s_hi += __shfl_xor_sync(0xffffffffu, s_hi, 1);
    s_hi += __shfl_xor_sync(0xffffffffu, s_hi, 2);

    // ---- step 3: O = A V (V via trans ldsm) ----
    float co[10][4];
#pragma unroll
    for (int j = 0; j < 10; j++)
#pragma unroll
        for (int e = 0; e < 4; e++) co[j][e] = 0.f;

#pragma unroll
    for (int ks2 = 0; ks2 < 8; ks2++) {
        uint32_t af[4];
        af[0] = packh2(ca[ks2 * 2 + 0][0], ca[ks2 * 2 + 0][1]);
        af[1] = packh2(ca[ks2 * 2 + 0][2], ca[ks2 * 2 + 0][3]);
        af[2] = packh2(ca[ks2 * 2 + 1][0], ca[ks2 * 2 + 1][1]);
        af[3] = packh2(ca[ks2 * 2 + 1][2], ca[ks2 * 2 + 1][3]);
#pragma unroll
        for (int fg = 0; fg < 4; fg++) {
            uint32_t bv[4];
            ldsm4t(bv, sb + OFF_V + (uint32_t)((ks2 * 16 + t_row) * QVP + (fg * 16 + t_col) * 2));
            mmaf16(co[fg * 2 + 0], af, &bv[0]);
            mmaf16(co[fg * 2 + 1], af, &bv[2]);
        }
    }

    // ---- step 4: O += Q [Sp | zp] ----
#pragma unroll
    for (int ks = 0; ks < 4; ks++) {
        uint32_t aq[4];
        ldsm4(aq, sb + OFF_Q + (uint32_t)((w * 16 + a_row) * QVP + (ks * 16 + a_koff) * 2));
#pragma unroll
        for (int fg = 0; fg < 5; fg++) {
            uint32_t bs[4];
            ldsm4t(bs, sb + OFF_SP + (uint32_t)((ks * 16 + t_row) * SPB + (fg * 16 + t_col) * 2));
            mmaf16(co[fg * 2 + 0], aq, &bs[0]);
            mmaf16(co[fg * 2 + 1], aq, &bs[2]);
        }
    }

    // ---- step 5: denominator, divide, write xo fp16 ----
    float qz_lo = __shfl_sync(0xffffffffu, co[8][0], lid & ~3);
    float qz_hi = __shfl_sync(0xffffffffu, co[8][2], lid & ~3);
    float inv_lo = 1.f / (s_lo + qz_lo + EPSF);
    float inv_hi = 1.f / (s_hi + qz_hi + EPSF);

#pragma unroll
    for (int j = 0; j < 8; j++) {
        int col = h * HS + j * 8 + tq * 2;
        size_t i_lo = (size_t)(t0g + row_lo) * D_MODEL + col;
        size_t i_hi = (size_t)(t0g + row_hi) * D_MODEL + col;
        *(uint32_t*)(g_xh + i_lo) = packh2(co[j][0] * inv_lo, co[j][1] * inv_lo);
        *(uint32_t*)(g_xh + i_hi) = packh2(co[j][2] * inv_hi, co[j][3] * inv_hi);
    }
}

// ---------------- launch ----------------
extern "C" void kernel_launch(void* const* d_in, const int* in_sizes, int n_in,
                              void* d_out, int out_size) {
    const float* x     = (const float*)d_in[0];
    const float* w_qkv = (const float*)d_in[1];
    const float* w_out = (const float*)d_in[2];
    float* out = (float*)d_out;

    __half *xh, *w1, *w2;
    cudaGetSymbolAddress((void**)&xh, g_xh);
    cudaGetSymbolAddress((void**)&w1, g_w1);
    cudaGetSymbolAddress((void**)&w2, g_w2);

    const int CHUNK_SMEM = 2 * CHUNK * HS * sizeof(float);
    cudaFuncSetAttribute(gemm_fp16<1>, cudaFuncAttributeMaxDynamicSharedMemorySize, GSMF);
    cudaFuncSetAttribute(gemm_fp16<0>, cudaFuncAttributeMaxDynamicSharedMemorySize, GSMF);
    cudaFuncSetAttribute(gemm2_fp16,   cudaFuncAttributeMaxDynamicSharedMemorySize, GSM2);
    cudaFuncSetAttribute(chunk_sums, cudaFuncAttributeMaxDynamicSharedMemorySize, CHUNK_SMEM);
    cudaFuncSetAttribute(attn_mma,   cudaFuncAttributeMaxDynamicSharedMemorySize, ATTN_SMEM_B);

    cvth<<<(T_LEN * D_MODEL / 4 + 255) / 256, 256>>>(x, xh, T_LEN * D_MODEL / 4);
    cvth<<<(3 * D_MODEL * D_MODEL / 4 + 255) / 256, 256>>>(w_qkv, w1, 3 * D_MODEL * D_MODEL / 4);
    cvth<<<(D_MODEL * D_MODEL / 4 + 255) / 256, 256>>>(w_out, w2, D_MODEL * D_MODEL / 4);

    // GEMM1: qkv = x @ w_qkv^T (fused phi + fp16 store)
    dim3 g1(3 * D_MODEL / 128, T_LEN / 128);   // (24, 16)
    gemm_fp16<1><<<g1, 256, GSMF>>>(xh, w1, nullptr, T_LEN, 3 * D_MODEL, D_MODEL);

    chunk_sums<<<H_NUM * NC, 256, CHUNK_SMEM>>>();
    chunk_prefix<<<H_NUM * 20, 256>>>();
    attn_mma<<<H_NUM * NC, 256, ATTN_SMEM_B>>>();   // writes xo fp16 into xh

    // GEMM2: out = xo @ w_out^T (64x128 tiles, 256 CTAs)
    dim3 g2(D_MODEL / 128, T_LEN / 64);        // (8, 32)
    gemm2_fp16<<<g2, 256, GSM2>>>(xh, w2, out, T_LEN, D_MODEL, D_MODEL);
}

// round 12
// speedup vs baseline: 4.9770x; 1.1273x over previous
#include <cuda_runtime.h>
#include <cuda_bf16.h>
#include <cuda_fp16.h>
#include <cstdint>

#define T_LEN 2048
#define D_MODEL 1024
#define H_NUM 16
#define HS 64
#define CHUNK 128
#define NC 16
#define EPSF 1e-6f
#define SCP 80

// ---------------- scratch ----------------
__device__ float g_Sc [H_NUM * NC * HS * SCP];
__device__ __align__(16) __half g_sp[H_NUM * NC * HS * SCP];     // prefix, fp16

__device__ __align__(16) __half g_qkv[3][H_NUM][T_LEN][HS];      // phi(q),phi(k),v fp16

__device__ __align__(16) __half g_xh[T_LEN * D_MODEL];           // x, then xo
__device__ __align__(16) __half g_w1[3 * D_MODEL * D_MODEL];
__device__ __align__(16) __half g_w2[D_MODEL * D_MODEL];

__device__ __forceinline__ float phi(float x) {
    return x > 0.f ? x + 1.f : expf(x);
}
__device__ __forceinline__ uint32_t packh2(float a, float b) {
    return (uint32_t)__half_as_ushort(__float2half_rn(a)) |
           ((uint32_t)__half_as_ushort(__float2half_rn(b)) << 16);
}

// fused fp32 -> fp16 for x, w_qkv, w_out (ranges in float4 chunks)
#define CVT_X  524288                 /* 2048*1024/4 */
#define CVT_W1 786432                 /* 3*1024*1024/4 */
#define CVT_W2 262144                 /* 1024*1024/4 */
#define CVT_TOTAL (CVT_X + CVT_W1 + CVT_W2)   /* 1572864 */
__global__ __launch_bounds__(256) void cvt_all(const float* __restrict__ x,
                                               const float* __restrict__ w1,
                                               const float* __restrict__ w2) {
    int i = blockIdx.x * 256 + threadIdx.x;
    const float* s;
    __half* d;
    int off;
    if (i < CVT_X)                { s = x;  d = g_xh; off = i; }
    else if (i < CVT_X + CVT_W1)  { s = w1; d = g_w1; off = i - CVT_X; }
    else                          { s = w2; d = g_w2; off = i - CVT_X - CVT_W1; }
    float4 v = ((const float4*)s)[off];
    ((uint2*)d)[off] = make_uint2(packh2(v.x, v.y), packh2(v.z, v.w));
}

// ---------------- mma helpers ----------------
__device__ __forceinline__ uint32_t smem_u32(const void* p) {
    uint32_t a;
    asm("{ .reg .u64 t; cvta.to.shared.u64 t, %1; cvt.u32.u64 %0, t; }" : "=r"(a) : "l"(p));
    return a;
}
__device__ __forceinline__ void ldsm4(uint32_t* r, uint32_t addr) {
    asm volatile("ldmatrix.sync.aligned.m8n8.x4.shared.b16 {%0,%1,%2,%3}, [%4];"
                 : "=r"(r[0]), "=r"(r[1]), "=r"(r[2]), "=r"(r[3]) : "r"(addr));
}
__device__ __forceinline__ void ldsm4t(uint32_t* r, uint32_t addr) {
    asm volatile("ldmatrix.sync.aligned.m8n8.x4.trans.shared.b16 {%0,%1,%2,%3}, [%4];"
                 : "=r"(r[0]), "=r"(r[1]), "=r"(r[2]), "=r"(r[3]) : "r"(addr));
}
__device__ __forceinline__ void mmaf16(float* d, const uint32_t* a, const uint32_t* b) {
    asm volatile("mma.sync.aligned.m16n8k16.row.col.f32.f16.f16.f32 "
                 "{%0,%1,%2,%3},{%4,%5,%6,%7},{%8,%9},{%0,%1,%2,%3};"
                 : "+f"(d[0]), "+f"(d[1]), "+f"(d[2]), "+f"(d[3])
                 : "r"(a[0]), "r"(a[1]), "r"(a[2]), "r"(a[3]), "r"(b[0]), "r"(b[1]));
}
#define CP16(dst, src) \
    asm volatile("cp.async.cg.shared.global [%0], [%1], 16;" :: "r"(dst), "l"(src) : "memory")
#define CP_COMMIT() asm volatile("cp.async.commit_group;" ::: "memory")
#define CP_WAIT0()  asm volatile("cp.async.wait_group 0;" ::: "memory")
#define CP_WAIT1()  asm volatile("cp.async.wait_group 1;" ::: "memory")

// ============================================================================
// GEMM1: fp16, CTA 128x128, 8 warps 32x64, BK=64, 3-stage pipeline, 2 CTA/SM.
// EPI=1: fused phi + fp16 store -> g_qkv. EPI=0: fp32 C.
// ============================================================================
#define FPITCH 144
#define FTILE (128 * FPITCH)             /* 18432 */
#define FSTAGE (2 * FTILE)               /* 36864 */
#define GSMF (3 * FSTAGE)                /* 110592 */

template<int EPI>
__global__ __launch_bounds__(256, 2) void gemm_fp16(
        const __half* __restrict__ A, const __half* __restrict__ B,
        float* __restrict__ C, int M, int N, int K) {
    extern __shared__ char smem[];
    const uint32_t sb = smem_u32(smem);

    const int tid = threadIdx.x;
    const int wid = tid >> 5, lid = tid & 31;
    const int warp_m = wid & 3, warp_n = wid >> 2;
    const int m0 = blockIdx.y * 128, n0 = blockIdx.x * 128;
    const int NKB = K >> 6;

    const int a_row  = lid & 15;
    const int a_koff = (lid >> 4) * 8;
    const int b_n    = (lid & 7) + ((lid >> 4) << 3);
    const int b_ko   = ((lid >> 3) & 1) * 8;
    const int g = lid >> 2, tg = lid & 3;

    float acc[2][8][4];
#pragma unroll
    for (int i = 0; i < 2; i++)
#pragma unroll
        for (int j = 0; j < 8; j++)
#pragma unroll
            for (int k = 0; k < 4; k++) acc[i][j][k] = 0.f;

    auto load_st = [&](uint32_t stg, int kb) {
#pragma unroll
        for (int j = 0; j < 8; j++) {
            int chunkid = tid + j * 256;
            int tile = chunkid >> 10;
            int within = chunkid & 1023;
            int row = within >> 3, c = within & 7;
            const __half* src = (tile ? B + (size_t)(n0 + row) * K
                                      : A + (size_t)(m0 + row) * K) + kb * 64 + c * 8;
            CP16(stg + tile * FTILE + row * FPITCH + c * 16, src);
        }
        CP_COMMIT();
    };

    load_st(sb, 0);
    load_st(sb + FSTAGE, 1);
    CP_WAIT1();
    __syncthreads();

#pragma unroll 1
    for (int kb = 0; kb < NKB; kb++) {
        if (kb + 2 < NKB) load_st(sb + ((kb + 2) % 3) * FSTAGE, kb + 2);

        const uint32_t stage = sb + (kb % 3) * FSTAGE;
        const uint32_t tA = stage;
        const uint32_t tB = stage + FTILE;

#pragma unroll
        for (int ks = 0; ks < 4; ks++) {
            uint32_t af[2][4];
#pragma unroll
            for (int mt = 0; mt < 2; mt++) {
                uint32_t ao = (uint32_t)((warp_m * 32 + mt * 16 + a_row) * FPITCH +
                                         (ks * 16 + a_koff) * 2);
                ldsm4(af[mt], tA + ao);
            }
            uint32_t bf[4][4];
#pragma unroll
            for (int ng = 0; ng < 4; ng++) {
                uint32_t bo = (uint32_t)((warp_n * 64 + ng * 16 + b_n) * FPITCH +
                                         (ks * 16 + b_ko) * 2);
                ldsm4(bf[ng], tB + bo);
            }
#pragma unroll
            for (int ng = 0; ng < 4; ng++)
#pragma unroll
                for (int mt = 0; mt < 2; mt++) {
                    mmaf16(acc[mt][ng * 2 + 0], af[mt], &bf[ng][0]);
                    mmaf16(acc[mt][ng * 2 + 1], af[mt], &bf[ng][2]);
                }
        }

        if (kb + 1 < NKB) {
            if (kb + 2 < NKB) CP_WAIT1(); else CP_WAIT0();
            __syncthreads();
        }
    }

    if (EPI) {
#pragma unroll
        for (int mt = 0; mt < 2; mt++) {
#pragma unroll
            for (int j = 0; j < 8; j++) {
                float* d = acc[mt][j];
                int n = n0 + warp_n * 64 + j * 8 + tg * 2;
                int sq = n >> 10, hh2 = (n >> 6) & 15, dd = n & 63;
                int r0 = m0 + warp_m * 32 + mt * 16 + g;
                float v0 = d[0], v1 = d[1], v2 = d[2], v3 = d[3];
                if (sq < 2) { v0 = phi(v0); v1 = phi(v1); v2 = phi(v2); v3 = phi(v3); }
                *(uint32_t*)&g_qkv[sq][hh2][r0][dd]     = packh2(v0, v1);
                *(uint32_t*)&g_qkv[sq][hh2][r0 + 8][dd] = packh2(v2, v3);
            }
        }
    } else {
#pragma unroll
        for (int mt = 0; mt < 2; mt++) {
#pragma unroll
            for (int j = 0; j < 8; j++) {
                float* d = acc[mt][j];
                int r0 = m0 + warp_m * 32 + mt * 16 + g;
                int col = n0 + warp_n * 64 + j * 8 + tg * 2;
                *(float2*)(C + (size_t)r0 * N + col)       = make_float2(d[0], d[1]);
                *(float2*)(C + (size_t)(r0 + 8) * N + col) = make_float2(d[2], d[3]);
            }
        }
    }
}

// ============================================================================
// GEMM2: fp16, CTA 64x128, 8 warps 32x32, BK=64, 3-stage, 2 CTA/SM.
// ============================================================================
#define G2A (64 * FPITCH)                /* 9216 */
#define G2B (128 * FPITCH)               /* 18432 */
#define G2STG (G2A + G2B)                /* 27648 */
#define GSM2 (3 * G2STG)                 /* 82944 */

__global__ __launch_bounds__(256, 2) void gemm2_fp16(
        const __half* __restrict__ A, const __half* __restrict__ B,
        float* __restrict__ C, int M, int N, int K) {
    extern __shared__ char smem[];
    const uint32_t sb = smem_u32(smem);

    const int tid = threadIdx.x;
    const int wid = tid >> 5, lid = tid & 31;
    const int warp_m = wid & 1, warp_n = wid >> 1;   // 2 x 4
    const int m0 = blockIdx.y * 64, n0 = blockIdx.x * 128;
    const int NKB = K >> 6;

    const int a_row  = lid & 15;
    const int a_koff = (lid >> 4) * 8;
    const int b_n    = (lid & 7) + ((lid >> 4) << 3);
    const int b_ko   = ((lid >> 3) & 1) * 8;
    const int g = lid >> 2, tg = lid & 3;

    float acc[2][4][4];
#pragma unroll
    for (int i = 0; i < 2; i++)
#pragma unroll
        for (int j = 0; j < 4; j++)
#pragma unroll
            for (int k = 0; k < 4; k++) acc[i][j][k] = 0.f;

    auto load_st = [&](uint32_t stg, int kb) {
#pragma unroll
        for (int j = 0; j < 6; j++) {
            int chunkid = tid + j * 256;               // 0..1535
            if (chunkid < 512) {
                int row = chunkid >> 3, c = chunkid & 7;
                CP16(stg + row * FPITCH + c * 16,
                     A + (size_t)(m0 + row) * K + kb * 64 + c * 8);
            } else {
                int cid = chunkid - 512;
                int row = cid >> 3, c = cid & 7;
                CP16(stg + G2A + row * FPITCH + c * 16,
                     B + (size_t)(n0 + row) * K + kb * 64 + c * 8);
            }
        }
        CP_COMMIT();
    };

    load_st(sb, 0);
    load_st(sb + G2STG, 1);
    CP_WAIT1();
    __syncthreads();

#pragma unroll 1
    for (int kb = 0; kb < NKB; kb++) {
        if (kb + 2 < NKB) load_st(sb + ((kb + 2) % 3) * G2STG, kb + 2);

        const uint32_t stage = sb + (kb % 3) * G2STG;

#pragma unroll
        for (int ks = 0; ks < 4; ks++) {
            uint32_t af[2][4];
#pragma unroll
            for (int mt = 0; mt < 2; mt++) {
                uint32_t ao = (uint32_t)((warp_m * 32 + mt * 16 + a_row) * FPITCH +
                                         (ks * 16 + a_koff) * 2);
                ldsm4(af[mt], stage + ao);
            }
            uint32_t bf[2][4];
#pragma unroll
            for (int nh = 0; nh < 2; nh++) {
                uint32_t bo = (uint32_t)((warp_n * 32 + nh * 16 + b_n) * FPITCH +
                                         (ks * 16 + b_ko) * 2);
                ldsm4(bf[nh], stage + G2A + bo);
            }
#pragma unroll
            for (int nh = 0; nh < 2; nh++)
#pragma unroll
                for (int mt = 0; mt < 2; mt++) {
                    mmaf16(acc[mt][nh * 2 + 0], af[mt], &bf[nh][0]);
                    mmaf16(acc[mt][nh * 2 + 1], af[mt], &bf[nh][2]);
                }
        }

        if (kb + 1 < NKB) {
            if (kb + 2 < NKB) CP_WAIT1(); else CP_WAIT0();
            __syncthreads();
        }
    }

#pragma unroll
    for (int mt = 0; mt < 2; mt++) {
#pragma unroll
        for (int j = 0; j < 4; j++) {
            float* d = acc[mt][j];
            int r0 = m0 + warp_m * 32 + mt * 16 + g;
            int col = n0 + warp_n * 32 + j * 8 + tg * 2;
            *(float2*)(C + (size_t)r0 * N + col)       = make_float2(d[0], d[1]);
            *(float2*)(C + (size_t)(r0 + 8) * N + col) = make_float2(d[2], d[3]);
        }
    }
}

// ============================================================================
// chunk_sums via fp16 mma: Sc[d][f] = sum_t K[t][d] V[t][f]; col 64 = zc
// (ones column in V). A = K^T and B = V^T, both via ldsm.trans.
// 128 threads (4 warps x m16), N covered by 5 fg groups (80 cols).
// ============================================================================
#define CSK 144
#define CSV 176
#define OFF_CK 0
#define OFF_CV (128 * CSK)               /* 18432 */
#define CS_SMEM (OFF_CV + 128 * CSV)     /* 41M? = 18432 + 22528 = 40960 */

__global__ __launch_bounds__(128) void chunk_sums() {
    extern __shared__ char smc[];
    const uint32_t sb = smem_u32(smc);
    const int blk = blockIdx.x;
    const int h = blk >> 4, cc = blk & 15;
    const int t0 = cc * CHUNK;
    const int tid = threadIdx.x;
    const int w = tid >> 5, lid = tid & 31;

#pragma unroll
    for (int j = 0; j < 8; j++) {        // K tile: 1024 chunks
        int cid = tid + j * 128;
        int row = cid >> 3, c = cid & 7;
        CP16(sb + OFF_CK + row * CSK + c * 16, &g_qkv[1][h][t0 + row][0] + c * 8);
    }
#pragma unroll
    for (int j = 0; j < 8; j++) {        // V tile: 1024 chunks
        int cid = tid + j * 128;
        int row = cid >> 3, c = cid & 7;
        CP16(sb + OFF_CV + row * CSV + c * 16, &g_qkv[2][h][t0 + row][0] + c * 8);
    }
    // cols 64-79 of V: col64 = 1.0 (zc via ones column), rest 0
    *(uint4*)(smc + OFF_CV + tid * CSV + 128) = make_uint4(0x00003C00u, 0u, 0u, 0u);
    *(uint4*)(smc + OFF_CV + tid * CSV + 144) = make_uint4(0u, 0u, 0u, 0u);
    CP_COMMIT();
    CP_WAIT0();
    __syncthreads();

    // A-trans addressing (m16k16 from [k][m] tile)
    const int at_row = (lid & 7) + ((lid >> 4) << 3);
    const int at_co  = ((lid >> 3) & 1) * 8;
    // B-trans addressing (n16k16 from [k][n] tile)
    const int bt_row = lid & 15;
    const int bt_co  = (lid >> 4) << 3;
    const int g = lid >> 2, tq = lid & 3;

    float acc[5][2][4];
#pragma unroll
    for (int fg = 0; fg < 5; fg++)
#pragma unroll
        for (int hf = 0; hf < 2; hf++)
#pragma unroll
            for (int e = 0; e < 4; e++) acc[fg][hf][e] = 0.f;

#pragma unroll
    for (int ks = 0; ks < 8; ks++) {
        uint32_t af[4];
        ldsm4t(af, sb + OFF_CK + (uint32_t)((ks * 16 + at_row) * CSK + (w * 16 + at_co) * 2));
#pragma unroll
        for (int fg = 0; fg < 5; fg++) {
            uint32_t bf[4];
            ldsm4t(bf, sb + OFF_CV + (uint32_t)((ks * 16 + bt_row) * CSV + (fg * 16 + bt_co) * 2));
            mmaf16(acc[fg][0], af, &bf[0]);
            mmaf16(acc[fg][1], af, &bf[2]);
        }
    }

    float* Sout = g_Sc + (size_t)blk * HS * SCP;
#pragma unroll
    for (int fg = 0; fg < 5; fg++)
#pragma unroll
        for (int hf = 0; hf < 2; hf++) {
            float* d = acc[fg][hf];
            int r = w * 16 + g;
            int col = fg * 16 + hf * 8 + tq * 2;
            *(float2*)&Sout[r * SCP + col]       = make_float2(d[0], d[1]);
            *(float2*)&Sout[(r + 8) * SCP + col] = make_float2(d[2], d[3]);
        }
}

// ---------------- exclusive prefix -> fp16 Sp ----------------
__global__ __launch_bounds__(256) void chunk_prefix() {
    int h = blockIdx.x / 20;
    int e = (blockIdx.x % 20) * 256 + threadIdx.x;
    float run = 0.f;
#pragma unroll
    for (int c = 0; c < NC; c++) {
        size_t idx = (size_t)(h * NC + c) * (HS * SCP) + e;
        g_sp[idx] = __float2half_rn(run);
        run += g_Sc[idx];
    }
}

// ============================================================================
// attention per chunk, single-limb fp16 mma (R11, unchanged)
// ============================================================================
#define QVP 144
#define SPB 176
#define OFF_Q 0
#define OFF_K (1 * 128 * QVP)
#define OFF_V (2 * 128 * QVP)
#define OFF_SP (3 * 128 * QVP)
#define ATTN_SMEM_B (OFF_SP + 64 * SPB)

__global__ __launch_bounds__(256, 2) void attn_mma() {
    extern __shared__ char smc[];
    const uint32_t sb = smem_u32(smc);

    const int blk = blockIdx.x;
    const int h = blk >> 4, cc = blk & 15;
    const int t0g = cc * CHUNK;
    const int tid = threadIdx.x;
    const int w = tid >> 5, lid = tid & 31;

#pragma unroll
    for (int j = 0; j < 12; j++) {
        int chunkid = tid + j * 256;
        int buf = chunkid >> 10;
        int within = chunkid & 1023;
        int row = within >> 3, c = within & 7;
        CP16(sb + buf * (128 * QVP) + row * QVP + c * 16,
             &g_qkv[buf][h][t0g + row][0] + c * 8);
    }
#pragma unroll
    for (int j = 0; j < 3; j++) {
        int chunkid = tid + j * 256;
        if (chunkid < 640) {
            int row = chunkid / 10, c = chunkid % 10;
            CP16(sb + OFF_SP + row * SPB + c * 16,
                 g_sp + (size_t)blk * (HS * SCP) + row * SCP + c * 8);
        }
    }
    CP_COMMIT();
    CP_WAIT0();
    __syncthreads();

    const int a_row  = lid & 15;
    const int a_koff = (lid >> 4) * 8;
    const int b_n    = (lid & 7) + ((lid >> 4) << 3);
    const int b_ko   = ((lid >> 3) & 1) * 8;
    const int t_row  = lid & 15;
    const int t_col  = ((lid >> 4) << 3);
    const int g = lid >> 2, tq = lid & 3;

    float ca[16][4];
#pragma unroll
    for (int j = 0; j < 16; j++)
#pragma unroll
        for (int e = 0; e < 4; e++) ca[j][e] = 0.f;

#pragma unroll
    for (int ks = 0; ks < 4; ks++) {
        uint32_t aq[4];
        ldsm4(aq, sb + OFF_Q + (uint32_t)((w * 16 + a_row) * QVP + (ks * 16 + a_koff) * 2));
#pragma unroll
        for (int sg = 0; sg < 8; sg++) {
            uint32_t bk[4];
            ldsm4(bk, sb + OFF_K + (uint32_t)((sg * 16 + b_n) * QVP + (ks * 16 + b_ko) * 2));
            mmaf16(ca[sg * 2 + 0], aq, &bk[0]);
            mmaf16(ca[sg * 2 + 1], aq, &bk[2]);
        }
    }

    const int row_lo = w * 16 + g, row_hi = row_lo + 8;
    float s_lo = 0.f, s_hi = 0.f;
#pragma unroll
    for (int j = 0; j < 16; j++) {
        int c0 = j * 8 + tq * 2;
        if (c0     > row_lo) ca[j][0] = 0.f;
        if (c0 + 1 > row_lo) ca[j][1] = 0.f;
        if (c0     > row_hi) ca[j][2] = 0.f;
        if (c0 + 1 > row_hi) ca[j][3] = 0.f;
        s_lo += ca[j][0] + ca[j][1];
        s_hi += ca[j][2] + ca[j][3];
    }
    s_lo += __shfl_xor_sync(0xffffffffu, s_lo, 1);
    s_lo += __shfl_xor_sync(0xffffffffu, s_lo, 2);
    s_hi += __shfl_xor_sync(0xffffffffu, s_hi, 1);
    s_hi += __shfl_xor_sync(0xffffffffu, s_hi, 2);

    float co[10][4];
#pragma unroll
    for (int j = 0; j < 10; j++)
#pragma unroll
        for (int e = 0; e < 4; e++) co[j][e] = 0.f;

#pragma unroll
    for (int ks2 = 0; ks2 < 8; ks2++) {
        uint32_t af[4];
        af[0] = packh2(ca[ks2 * 2 + 0][0], ca[ks2 * 2 + 0][1]);
        af[1] = packh2(ca[ks2 * 2 + 0][2], ca[ks2 * 2 + 0][3]);
        af[2] = packh2(ca[ks2 * 2 + 1][0], ca[ks2 * 2 + 1][1]);
        af[3] = packh2(ca[ks2 * 2 + 1][2], ca[ks2 * 2 + 1][3]);
#pragma unroll
        for (int fg = 0; fg < 4; fg++) {
            uint32_t bv[4];
            ldsm4t(bv, sb + OFF_V + (uint32_t)((ks2 * 16 + t_row) * QVP + (fg * 16 + t_col) * 2));
            mmaf16(co[fg * 2 + 0], af, &bv[0]);
            mmaf16(co[fg * 2 + 1], af, &bv[2]);
        }
    }

#pragma unroll
    for (int ks = 0; ks < 4; ks++) {
        uint32_t aq[4];
        ldsm4(aq, sb + OFF_Q + (uint32_t)((w * 16 + a_row) * QVP + (ks * 16 + a_koff) * 2));
#pragma unroll
        for (int fg = 0; fg < 5; fg++) {
            uint32_t bs[4];
            ldsm4t(bs, sb + OFF_SP + (uint32_t)((ks * 16 + t_row) * SPB + (fg * 16 + t_col) * 2));
            mmaf16(co[fg * 2 + 0], aq, &bs[0]);
            mmaf16(co[fg * 2 + 1], aq, &bs[2]);
        }
    }

    float qz_lo = __shfl_sync(0xffffffffu, co[8][0], lid & ~3);
    float qz_hi = __shfl_sync(0xffffffffu, co[8][2], lid & ~3);
    float inv_lo = 1.f / (s_lo + qz_lo + EPSF);
    float inv_hi = 1.f / (s_hi + qz_hi + EPSF);

#pragma unroll
    for (int j = 0; j < 8; j++) {
        int col = h * HS + j * 8 + tq * 2;
        size_t i_lo = (size_t)(t0g + row_lo) * D_MODEL + col;
        size_t i_hi = (size_t)(t0g + row_hi) * D_MODEL + col;
        *(uint32_t*)(g_xh + i_lo) = packh2(co[j][0] * inv_lo, co[j][1] * inv_lo);
        *(uint32_t*)(g_xh + i_hi) = packh2(co[j][2] * inv_hi, co[j][3] * inv_hi);
    }
}

// ---------------- launch ----------------
extern "C" void kernel_launch(void* const* d_in, const int* in_sizes, int n_in,
                              void* d_out, int out_size) {
    const float* x     = (const float*)d_in[0];
    const float* w_qkv = (const float*)d_in[1];
    const float* w_out = (const float*)d_in[2];
    float* out = (float*)d_out;

    __half *xh, *w1, *w2;
    cudaGetSymbolAddress((void**)&xh, g_xh);
    cudaGetSymbolAddress((void**)&w1, g_w1);
    cudaGetSymbolAddress((void**)&w2, g_w2);

    cudaFuncSetAttribute(gemm_fp16<1>, cudaFuncAttributeMaxDynamicSharedMemorySize, GSMF);
    cudaFuncSetAttribute(gemm_fp16<0>, cudaFuncAttributeMaxDynamicSharedMemorySize, GSMF);
    cudaFuncSetAttribute(gemm2_fp16,   cudaFuncAttributeMaxDynamicSharedMemorySize, GSM2);
    cudaFuncSetAttribute(chunk_sums,   cudaFuncAttributeMaxDynamicSharedMemorySize, CS_SMEM);
    cudaFuncSetAttribute(attn_mma,     cudaFuncAttributeMaxDynamicSharedMemorySize, ATTN_SMEM_B);

    cvt_all<<<CVT_TOTAL / 256, 256>>>(x, w_qkv, w_out);

    // GEMM1: qkv = x @ w_qkv^T (fused phi + fp16 store)
    dim3 g1(3 * D_MODEL / 128, T_LEN / 128);   // (24, 16)
    gemm_fp16<1><<<g1, 256, GSMF>>>(xh, w1, nullptr, T_LEN, 3 * D_MODEL, D_MODEL);

    chunk_sums<<<H_NUM * NC, 128, CS_SMEM>>>();
    chunk_prefix<<<H_NUM * 20, 256>>>();
    attn_mma<<<H_NUM * NC, 256, ATTN_SMEM_B>>>();   // writes xo fp16 into xh

    // GEMM2: out = xo @ w_out^T
    dim3 g2(D_MODEL / 128, T_LEN / 64);        // (8, 32)
    gemm2_fp16<<<g2, 256, GSM2>>>(xh, w2, out, T_LEN, D_MODEL, D_MODEL);
}

// round 13
// speedup vs baseline: 5.0747x; 1.0196x over previous
#include <cuda_runtime.h>
#include <cuda_bf16.h>
#include <cuda_fp16.h>
#include <cstdint>

#define T_LEN 2048
#define D_MODEL 1024
#define H_NUM 16
#define HS 64
#define CHUNK 128
#define NC 16
#define EPSF 1e-6f
#define SCP 80

// ---------------- scratch ----------------
__device__ float g_Sc [H_NUM * NC * HS * SCP];
__device__ __align__(16) __half g_sp[H_NUM * NC * HS * SCP];     // prefix, fp16

__device__ __align__(16) __half g_qkv[3][H_NUM][T_LEN][HS];      // phi(q),phi(k),v fp16

__device__ __align__(16) __half g_xh[T_LEN * D_MODEL];           // x, then xo
__device__ __align__(16) __half g_w1[3 * D_MODEL * D_MODEL];
__device__ __align__(16) __half g_w2[D_MODEL * D_MODEL];

__device__ __forceinline__ float phi(float x) {
    return x > 0.f ? x + 1.f : expf(x);
}
__device__ __forceinline__ uint32_t packh2(float a, float b) {
    return (uint32_t)__half_as_ushort(__float2half_rn(a)) |
           ((uint32_t)__half_as_ushort(__float2half_rn(b)) << 16);
}

// fused fp32 -> fp16 for x, w_qkv, w_out (ranges in float4 chunks)
#define CVT_X  524288                 /* 2048*1024/4 */
#define CVT_W1 786432                 /* 3*1024*1024/4 */
#define CVT_W2 262144                 /* 1024*1024/4 */
#define CVT_TOTAL (CVT_X + CVT_W1 + CVT_W2)
__global__ __launch_bounds__(256) void cvt_all(const float* __restrict__ x,
                                               const float* __restrict__ w1,
                                               const float* __restrict__ w2) {
    int i = blockIdx.x * 256 + threadIdx.x;
    const float* s;
    __half* d;
    int off;
    if (i < CVT_X)                { s = x;  d = g_xh; off = i; }
    else if (i < CVT_X + CVT_W1)  { s = w1; d = g_w1; off = i - CVT_X; }
    else                          { s = w2; d = g_w2; off = i - CVT_X - CVT_W1; }
    float4 v = ((const float4*)s)[off];
    ((uint2*)d)[off] = make_uint2(packh2(v.x, v.y), packh2(v.z, v.w));
}

// ---------------- mma helpers ----------------
__device__ __forceinline__ uint32_t smem_u32(const void* p) {
    uint32_t a;
    asm("{ .reg .u64 t; cvta.to.shared.u64 t, %1; cvt.u32.u64 %0, t; }" : "=r"(a) : "l"(p));
    return a;
}
__device__ __forceinline__ void ldsm4(uint32_t* r, uint32_t addr) {
    asm volatile("ldmatrix.sync.aligned.m8n8.x4.shared.b16 {%0,%1,%2,%3}, [%4];"
                 : "=r"(r[0]), "=r"(r[1]), "=r"(r[2]), "=r"(r[3]) : "r"(addr));
}
__device__ __forceinline__ void ldsm4t(uint32_t* r, uint32_t addr) {
    asm volatile("ldmatrix.sync.aligned.m8n8.x4.trans.shared.b16 {%0,%1,%2,%3}, [%4];"
                 : "=r"(r[0]), "=r"(r[1]), "=r"(r[2]), "=r"(r[3]) : "r"(addr));
}
__device__ __forceinline__ void mmaf16(float* d, const uint32_t* a, const uint32_t* b) {
    asm volatile("mma.sync.aligned.m16n8k16.row.col.f32.f16.f16.f32 "
                 "{%0,%1,%2,%3},{%4,%5,%6,%7},{%8,%9},{%0,%1,%2,%3};"
                 : "+f"(d[0]), "+f"(d[1]), "+f"(d[2]), "+f"(d[3])
                 : "r"(a[0]), "r"(a[1]), "r"(a[2]), "r"(a[3]), "r"(b[0]), "r"(b[1]));
}
#define CP16(dst, src) \
    asm volatile("cp.async.cg.shared.global [%0], [%1], 16;" :: "r"(dst), "l"(src) : "memory")
#define CP_COMMIT() asm volatile("cp.async.commit_group;" ::: "memory")
#define CP_WAIT0()  asm volatile("cp.async.wait_group 0;" ::: "memory")
#define CP_WAIT1()  asm volatile("cp.async.wait_group 1;" ::: "memory")

// ============================================================================
// GEMM1: fp16, CTA 128x128, 8 warps 32x64, BK=64, 3-stage pipeline, 2 CTA/SM.
// ============================================================================
#define FPITCH 144
#define FTILE (128 * FPITCH)
#define FSTAGE (2 * FTILE)
#define GSMF (3 * FSTAGE)

template<int EPI>
__global__ __launch_bounds__(256, 2) void gemm_fp16(
        const __half* __restrict__ A, const __half* __restrict__ B,
        float* __restrict__ C, int M, int N, int K) {
    extern __shared__ char smem[];
    const uint32_t sb = smem_u32(smem);

    const int tid = threadIdx.x;
    const int wid = tid >> 5, lid = tid & 31;
    const int warp_m = wid & 3, warp_n = wid >> 2;
    const int m0 = blockIdx.y * 128, n0 = blockIdx.x * 128;
    const int NKB = K >> 6;

    const int a_row  = lid & 15;
    const int a_koff = (lid >> 4) * 8;
    const int b_n    = (lid & 7) + ((lid >> 4) << 3);
    const int b_ko   = ((lid >> 3) & 1) * 8;
    const int g = lid >> 2, tg = lid & 3;

    float acc[2][8][4];
#pragma unroll
    for (int i = 0; i < 2; i++)
#pragma unroll
        for (int j = 0; j < 8; j++)
#pragma unroll
            for (int k = 0; k < 4; k++) acc[i][j][k] = 0.f;

    auto load_st = [&](uint32_t stg, int kb) {
#pragma unroll
        for (int j = 0; j < 8; j++) {
            int chunkid = tid + j * 256;
            int tile = chunkid >> 10;
            int within = chunkid & 1023;
            int row = within >> 3, c = within & 7;
            const __half* src = (tile ? B + (size_t)(n0 + row) * K
                                      : A + (size_t)(m0 + row) * K) + kb * 64 + c * 8;
            CP16(stg + tile * FTILE + row * FPITCH + c * 16, src);
        }
        CP_COMMIT();
    };

    load_st(sb, 0);
    load_st(sb + FSTAGE, 1);
    CP_WAIT1();
    __syncthreads();

#pragma unroll 1
    for (int kb = 0; kb < NKB; kb++) {
        if (kb + 2 < NKB) load_st(sb + ((kb + 2) % 3) * FSTAGE, kb + 2);

        const uint32_t stage = sb + (kb % 3) * FSTAGE;
        const uint32_t tA = stage;
        const uint32_t tB = stage + FTILE;

#pragma unroll
        for (int ks = 0; ks < 4; ks++) {
            uint32_t af[2][4];
#pragma unroll
            for (int mt = 0; mt < 2; mt++) {
                uint32_t ao = (uint32_t)((warp_m * 32 + mt * 16 + a_row) * FPITCH +
                                         (ks * 16 + a_koff) * 2);
                ldsm4(af[mt], tA + ao);
            }
            uint32_t bf[4][4];
#pragma unroll
            for (int ng = 0; ng < 4; ng++) {
                uint32_t bo = (uint32_t)((warp_n * 64 + ng * 16 + b_n) * FPITCH +
                                         (ks * 16 + b_ko) * 2);
                ldsm4(bf[ng], tB + bo);
            }
#pragma unroll
            for (int ng = 0; ng < 4; ng++)
#pragma unroll
                for (int mt = 0; mt < 2; mt++) {
                    mmaf16(acc[mt][ng * 2 + 0], af[mt], &bf[ng][0]);
                    mmaf16(acc[mt][ng * 2 + 1], af[mt], &bf[ng][2]);
                }
        }

        if (kb + 1 < NKB) {
            if (kb + 2 < NKB) CP_WAIT1(); else CP_WAIT0();
            __syncthreads();
        }
    }

    if (EPI) {
#pragma unroll
        for (int mt = 0; mt < 2; mt++) {
#pragma unroll
            for (int j = 0; j < 8; j++) {
                float* d = acc[mt][j];
                int n = n0 + warp_n * 64 + j * 8 + tg * 2;
                int sq = n >> 10, hh2 = (n >> 6) & 15, dd = n & 63;
                int r0 = m0 + warp_m * 32 + mt * 16 + g;
                float v0 = d[0], v1 = d[1], v2 = d[2], v3 = d[3];
                if (sq < 2) { v0 = phi(v0); v1 = phi(v1); v2 = phi(v2); v3 = phi(v3); }
                *(uint32_t*)&g_qkv[sq][hh2][r0][dd]     = packh2(v0, v1);
                *(uint32_t*)&g_qkv[sq][hh2][r0 + 8][dd] = packh2(v2, v3);
            }
        }
    } else {
#pragma unroll
        for (int mt = 0; mt < 2; mt++) {
#pragma unroll
            for (int j = 0; j < 8; j++) {
                float* d = acc[mt][j];
                int r0 = m0 + warp_m * 32 + mt * 16 + g;
                int col = n0 + warp_n * 64 + j * 8 + tg * 2;
                *(float2*)(C + (size_t)r0 * N + col)       = make_float2(d[0], d[1]);
                *(float2*)(C + (size_t)(r0 + 8) * N + col) = make_float2(d[2], d[3]);
            }
        }
    }
}

// ============================================================================
// GEMM2: fp16, CTA 64x128, 8 warps 32x32, BK=64, 3-stage, 2 CTA/SM.
// ============================================================================
#define G2A (64 * FPITCH)
#define G2B (128 * FPITCH)
#define G2STG (G2A + G2B)
#define GSM2 (3 * G2STG)

__global__ __launch_bounds__(256, 2) void gemm2_fp16(
        const __half* __restrict__ A, const __half* __restrict__ B,
        float* __restrict__ C, int M, int N, int K) {
    extern __shared__ char smem[];
    const uint32_t sb = smem_u32(smem);

    const int tid = threadIdx.x;
    const int wid = tid >> 5, lid = tid & 31;
    const int warp_m = wid & 1, warp_n = wid >> 1;
    const int m0 = blockIdx.y * 64, n0 = blockIdx.x * 128;
    const int NKB = K >> 6;

    const int a_row  = lid & 15;
    const int a_koff = (lid >> 4) * 8;
    const int b_n    = (lid & 7) + ((lid >> 4) << 3);
    const int b_ko   = ((lid >> 3) & 1) * 8;
    const int g = lid >> 2, tg = lid & 3;

    float acc[2][4][4];
#pragma unroll
    for (int i = 0; i < 2; i++)
#pragma unroll
        for (int j = 0; j < 4; j++)
#pragma unroll
            for (int k = 0; k < 4; k++) acc[i][j][k] = 0.f;

    auto load_st = [&](uint32_t stg, int kb) {
#pragma unroll
        for (int j = 0; j < 6; j++) {
            int chunkid = tid + j * 256;
            if (chunkid < 512) {
                int row = chunkid >> 3, c = chunkid & 7;
                CP16(stg + row * FPITCH + c * 16,
                     A + (size_t)(m0 + row) * K + kb * 64 + c * 8);
            } else {
                int cid = chunkid - 512;
                int row = cid >> 3, c = cid & 7;
                CP16(stg + G2A + row * FPITCH + c * 16,
                     B + (size_t)(n0 + row) * K + kb * 64 + c * 8);
            }
        }
        CP_COMMIT();
    };

    load_st(sb, 0);
    load_st(sb + G2STG, 1);
    CP_WAIT1();
    __syncthreads();

#pragma unroll 1
    for (int kb = 0; kb < NKB; kb++) {
        if (kb + 2 < NKB) load_st(sb + ((kb + 2) % 3) * G2STG, kb + 2);

        const uint32_t stage = sb + (kb % 3) * G2STG;

#pragma unroll
        for (int ks = 0; ks < 4; ks++) {
            uint32_t af[2][4];
#pragma unroll
            for (int mt = 0; mt < 2; mt++) {
                uint32_t ao = (uint32_t)((warp_m * 32 + mt * 16 + a_row) * FPITCH +
                                         (ks * 16 + a_koff) * 2);
                ldsm4(af[mt], stage + ao);
            }
            uint32_t bf[2][4];
#pragma unroll
            for (int nh = 0; nh < 2; nh++) {
                uint32_t bo = (uint32_t)((warp_n * 32 + nh * 16 + b_n) * FPITCH +
                                         (ks * 16 + b_ko) * 2);
                ldsm4(bf[nh], stage + G2A + bo);
            }
#pragma unroll
            for (int nh = 0; nh < 2; nh++)
#pragma unroll
                for (int mt = 0; mt < 2; mt++) {
                    mmaf16(acc[mt][nh * 2 + 0], af[mt], &bf[nh][0]);
                    mmaf16(acc[mt][nh * 2 + 1], af[mt], &bf[nh][2]);
                }
        }

        if (kb + 1 < NKB) {
            if (kb + 2 < NKB) CP_WAIT1(); else CP_WAIT0();
            __syncthreads();
        }
    }

#pragma unroll
    for (int mt = 0; mt < 2; mt++) {
#pragma unroll
        for (int j = 0; j < 4; j++) {
            float* d = acc[mt][j];
            int r0 = m0 + warp_m * 32 + mt * 16 + g;
            int col = n0 + warp_n * 32 + j * 8 + tg * 2;
            *(float2*)(C + (size_t)r0 * N + col)       = make_float2(d[0], d[1]);
            *(float2*)(C + (size_t)(r0 + 8) * N + col) = make_float2(d[2], d[3]);
        }
    }
}

// ============================================================================
// chunk_sums via fp16 mma (R12, unchanged)
// ============================================================================
#define CSK 144
#define CSV 176
#define OFF_CK 0
#define OFF_CV (128 * CSK)
#define CS_SMEM (OFF_CV + 128 * CSV)

__global__ __launch_bounds__(128) void chunk_sums() {
    extern __shared__ char smc[];
    const uint32_t sb = smem_u32(smc);
    const int blk = blockIdx.x;
    const int h = blk >> 4, cc = blk & 15;
    const int t0 = cc * CHUNK;
    const int tid = threadIdx.x;
    const int w = tid >> 5, lid = tid & 31;

#pragma unroll
    for (int j = 0; j < 8; j++) {
        int cid = tid + j * 128;
        int row = cid >> 3, c = cid & 7;
        CP16(sb + OFF_CK + row * CSK + c * 16, &g_qkv[1][h][t0 + row][0] + c * 8);
    }
#pragma unroll
    for (int j = 0; j < 8; j++) {
        int cid = tid + j * 128;
        int row = cid >> 3, c = cid & 7;
        CP16(sb + OFF_CV + row * CSV + c * 16, &g_qkv[2][h][t0 + row][0] + c * 8);
    }
    *(uint4*)(smc + OFF_CV + tid * CSV + 128) = make_uint4(0x00003C00u, 0u, 0u, 0u);
    *(uint4*)(smc + OFF_CV + tid * CSV + 144) = make_uint4(0u, 0u, 0u, 0u);
    CP_COMMIT();
    CP_WAIT0();
    __syncthreads();

    const int at_row = (lid & 7) + ((lid >> 4) << 3);
    const int at_co  = ((lid >> 3) & 1) * 8;
    const int bt_row = lid & 15;
    const int bt_co  = (lid >> 4) << 3;
    const int g = lid >> 2, tq = lid & 3;

    float acc[5][2][4];
#pragma unroll
    for (int fg = 0; fg < 5; fg++)
#pragma unroll
        for (int hf = 0; hf < 2; hf++)
#pragma unroll
            for (int e = 0; e < 4; e++) acc[fg][hf][e] = 0.f;

#pragma unroll
    for (int ks = 0; ks < 8; ks++) {
        uint32_t af[4];
        ldsm4t(af, sb + OFF_CK + (uint32_t)((ks * 16 + at_row) * CSK + (w * 16 + at_co) * 2));
#pragma unroll
        for (int fg = 0; fg < 5; fg++) {
            uint32_t bf[4];
            ldsm4t(bf, sb + OFF_CV + (uint32_t)((ks * 16 + bt_row) * CSV + (fg * 16 + bt_co) * 2));
            mmaf16(acc[fg][0], af, &bf[0]);
            mmaf16(acc[fg][1], af, &bf[2]);
        }
    }

    float* Sout = g_Sc + (size_t)blk * HS * SCP;
#pragma unroll
    for (int fg = 0; fg < 5; fg++)
#pragma unroll
        for (int hf = 0; hf < 2; hf++) {
            float* d = acc[fg][hf];
            int r = w * 16 + g;
            int col = fg * 16 + hf * 8 + tq * 2;
            *(float2*)&Sout[r * SCP + col]       = make_float2(d[0], d[1]);
            *(float2*)&Sout[(r + 8) * SCP + col] = make_float2(d[2], d[3]);
        }
}

// ---------------- exclusive prefix -> fp16 Sp (MLP-16 prefetch) ----------------
__global__ __launch_bounds__(256) void chunk_prefix() {
    int h = blockIdx.x / 20;
    int e = (blockIdx.x % 20) * 256 + threadIdx.x;
    const float* src = g_Sc + (size_t)h * NC * (HS * SCP) + e;
    __half* dst = g_sp + (size_t)h * NC * (HS * SCP) + e;

    float v[NC];
#pragma unroll
    for (int c = 0; c < NC; c++)
        v[c] = src[(size_t)c * (HS * SCP)];      // 16 independent loads in flight

    float run = 0.f;
#pragma unroll
    for (int c = 0; c < NC; c++) {
        dst[(size_t)c * (HS * SCP)] = __float2half_rn(run);
        run += v[c];
    }
}

// ============================================================================
// attention per chunk, single-limb fp16 mma (unchanged)
// ============================================================================
#define QVP 144
#define SPB 176
#define OFF_Q 0
#define OFF_K (1 * 128 * QVP)
#define OFF_V (2 * 128 * QVP)
#define OFF_SP (3 * 128 * QVP)
#define ATTN_SMEM_B (OFF_SP + 64 * SPB)

__global__ __launch_bounds__(256, 2) void attn_mma() {
    extern __shared__ char smc[];
    const uint32_t sb = smem_u32(smc);

    const int blk = blockIdx.x;
    const int h = blk >> 4, cc = blk & 15;
    const int t0g = cc * CHUNK;
    const int tid = threadIdx.x;
    const int w = tid >> 5, lid = tid & 31;

#pragma unroll
    for (int j = 0; j < 12; j++) {
        int chunkid = tid + j * 256;
        int buf = chunkid >> 10;
        int within = chunkid & 1023;
        int row = within >> 3, c = within & 7;
        CP16(sb + buf * (128 * QVP) + row * QVP + c * 16,
             &g_qkv[buf][h][t0g + row][0] + c * 8);
    }
#pragma unroll
    for (int j = 0; j < 3; j++) {
        int chunkid = tid + j * 256;
        if (chunkid < 640) {
            int row = chunkid / 10, c = chunkid % 10;
            CP16(sb + OFF_SP + row * SPB + c * 16,
                 g_sp + (size_t)blk * (HS * SCP) + row * SCP + c * 8);
        }
    }
    CP_COMMIT();
    CP_WAIT0();
    __syncthreads();

    const int a_row  = lid & 15;
    const int a_koff = (lid >> 4) * 8;
    const int b_n    = (lid & 7) + ((lid >> 4) << 3);
    const int b_ko   = ((lid >> 3) & 1) * 8;
    const int t_row  = lid & 15;
    const int t_col  = ((lid >> 4) << 3);
    const int g = lid >> 2, tq = lid & 3;

    float ca[16][4];
#pragma unroll
    for (int j = 0; j < 16; j++)
#pragma unroll
        for (int e = 0; e < 4; e++) ca[j][e] = 0.f;

#pragma unroll
    for (int ks = 0; ks < 4; ks++) {
        uint32_t aq[4];
        ldsm4(aq, sb + OFF_Q + (uint32_t)((w * 16 + a_row) * QVP + (ks * 16 + a_koff) * 2));
#pragma unroll
        for (int sg = 0; sg < 8; sg++) {
            uint32_t bk[4];
            ldsm4(bk, sb + OFF_K + (uint32_t)((sg * 16 + b_n) * QVP + (ks * 16 + b_ko) * 2));
            mmaf16(ca[sg * 2 + 0], aq, &bk[0]);
            mmaf16(ca[sg * 2 + 1], aq, &bk[2]);
        }
    }

    const int row_lo = w * 16 + g, row_hi = row_lo + 8;
    float s_lo = 0.f, s_hi = 0.f;
#pragma unroll
    for (int j = 0; j < 16; j++) {
        int c0 = j * 8 + tq * 2;
        if (c0     > row_lo) ca[j][0] = 0.f;
        if (c0 + 1 > row_lo) ca[j][1] = 0.f;
        if (c0     > row_hi) ca[j][2] = 0.f;
        if (c0 + 1 > row_hi) ca[j][3] = 0.f;
        s_lo += ca[j][0] + ca[j][1];
        s_hi += ca[j][2] + ca[j][3];
    }
    s_lo += __shfl_xor_sync(0xffffffffu, s_lo, 1);
    s_lo += __shfl_xor_sync(0xffffffffu, s_lo, 2);
    s_hi += __shfl_xor_sync(0xffffffffu, s_hi, 1);
    s_hi += __shfl_xor_sync(0xffffffffu, s_hi, 2);

    float co[10][4];
#pragma unroll
    for (int j = 0; j < 10; j++)
#pragma unroll
        for (int e = 0; e < 4; e++) co[j][e] = 0.f;

#pragma unroll
    for (int ks2 = 0; ks2 < 8; ks2++) {
        uint32_t af[4];
        af[0] = packh2(ca[ks2 * 2 + 0][0], ca[ks2 * 2 + 0][1]);
        af[1] = packh2(ca[ks2 * 2 + 0][2], ca[ks2 * 2 + 0][3]);
        af[2] = packh2(ca[ks2 * 2 + 1][0], ca[ks2 * 2 + 1][1]);
        af[3] = packh2(ca[ks2 * 2 + 1][2], ca[ks2 * 2 + 1][3]);
#pragma unroll
        for (int fg = 0; fg < 4; fg++) {
            uint32_t bv[4];
            ldsm4t(bv, sb + OFF_V + (uint32_t)((ks2 * 16 + t_row) * QVP + (fg * 16 + t_col) * 2));
            mmaf16(co[fg * 2 + 0], af, &bv[0]);
            mmaf16(co[fg * 2 + 1], af, &bv[2]);
        }
    }

#pragma unroll
    for (int ks = 0; ks < 4; ks++) {
        uint32_t aq[4];
        ldsm4(aq, sb + OFF_Q + (uint32_t)((w * 16 + a_row) * QVP + (ks * 16 + a_koff) * 2));
#pragma unroll
        for (int fg = 0; fg < 5; fg++) {
            uint32_t bs[4];
            ldsm4t(bs, sb + OFF_SP + (uint32_t)((ks * 16 + t_row) * SPB + (fg * 16 + t_col) * 2));
            mmaf16(co[fg * 2 + 0], aq, &bs[0]);
            mmaf16(co[fg * 2 + 1], aq, &bs[2]);
        }
    }

    float qz_lo = __shfl_sync(0xffffffffu, co[8][0], lid & ~3);
    float qz_hi = __shfl_sync(0xffffffffu, co[8][2], lid & ~3);
    float inv_lo = 1.f / (s_lo + qz_lo + EPSF);
    float inv_hi = 1.f / (s_hi + qz_hi + EPSF);

#pragma unroll
    for (int j = 0; j < 8; j++) {
        int col = h * HS + j * 8 + tq * 2;
        size_t i_lo = (size_t)(t0g + row_lo) * D_MODEL + col;
        size_t i_hi = (size_t)(t0g + row_hi) * D_MODEL + col;
        *(uint32_t*)(g_xh + i_lo) = packh2(co[j][0] * inv_lo, co[j][1] * inv_lo);
        *(uint32_t*)(g_xh + i_hi) = packh2(co[j][2] * inv_hi, co[j][3] * inv_hi);
    }
}

// ---------------- launch ----------------
extern "C" void kernel_launch(void* const* d_in, const int* in_sizes, int n_in,
                              void* d_out, int out_size) {
    const float* x     = (const float*)d_in[0];
    const float* w_qkv = (const float*)d_in[1];
    const float* w_out = (const float*)d_in[2];
    float* out = (float*)d_out;

    __half *xh, *w1, *w2;
    cudaGetSymbolAddress((void**)&xh, g_xh);
    cudaGetSymbolAddress((void**)&w1, g_w1);
    cudaGetSymbolAddress((void**)&w2, g_w2);

    cudaFuncSetAttribute(gemm_fp16<1>, cudaFuncAttributeMaxDynamicSharedMemorySize, GSMF);
    cudaFuncSetAttribute(gemm_fp16<0>, cudaFuncAttributeMaxDynamicSharedMemorySize, GSMF);
    cudaFuncSetAttribute(gemm2_fp16,   cudaFuncAttributeMaxDynamicSharedMemorySize, GSM2);
    cudaFuncSetAttribute(chunk_sums,   cudaFuncAttributeMaxDynamicSharedMemorySize, CS_SMEM);
    cudaFuncSetAttribute(attn_mma,     cudaFuncAttributeMaxDynamicSharedMemorySize, ATTN_SMEM_B);

    cvt_all<<<CVT_TOTAL / 256, 256>>>(x, w_qkv, w_out);

    dim3 g1(3 * D_MODEL / 128, T_LEN / 128);   // (24, 16)
    gemm_fp16<1><<<g1, 256, GSMF>>>(xh, w1, nullptr, T_LEN, 3 * D_MODEL, D_MODEL);

    chunk_sums<<<H_NUM * NC, 128, CS_SMEM>>>();
    chunk_prefix<<<H_NUM * 20, 256>>>();
    attn_mma<<<H_NUM * NC, 256, ATTN_SMEM_B>>>();

    dim3 g2(D_MODEL / 128, T_LEN / 64);        // (8, 32)
    gemm2_fp16<<<g2, 256, GSM2>>>(xh, w2, out, T_LEN, D_MODEL, D_MODEL);
}